// round 1
// baseline (speedup 1.0000x reference)
#include <cuda_runtime.h>
#include <math.h>

#define S_LEN 2048
#define BATCH 2
#define EMB   1024
#define HEADS 16
#define HDIM  64
#define NROWS (BATCH*S_LEN)   // 4096

// Scratch (no allocations allowed)
__device__ float g_q[(size_t)BATCH*HEADS*S_LEN*HDIM];   // [bh][s][d], pre-scaled by 1/sqrt(D)
__device__ float g_k[(size_t)BATCH*HEADS*S_LEN*HDIM];
__device__ float g_v[(size_t)BATCH*HEADS*S_LEN*HDIM];
__device__ float g_ctx[(size_t)NROWS*EMB];              // [b*S+s][e]

// ---------------------------------------------------------------------------
// Tiled SGEMM, 128x128x16 tiles, 256 threads, 8x8 per-thread microtile.
// MODE 0: C = X@Wqk + bias  -> scatter to g_q (scaled 0.125) / g_k   (N=2048)
// MODE 1: C = X@Wv;  v = gr*C + gs*X -> scatter to g_v               (N=1024)
// MODE 2: C = ctx@Wp; out = gr*C + gs*ctx -> outp                    (N=1024)
// ---------------------------------------------------------------------------
template<int MODE, int N>
__global__ __launch_bounds__(256) void sgemm_k(
    const float* __restrict__ A, const float* __restrict__ W,
    const float* __restrict__ bias,
    const float* __restrict__ grp, const float* __restrict__ gsp,
    float* __restrict__ outp)
{
    constexpr int K = 1024;
    __shared__ float As[16][128];
    __shared__ float Bs[16][128];

    const float* Ap = (MODE == 2) ? g_ctx : A;

    int tid = threadIdx.x;
    int ty = tid >> 4, tx = tid & 15;
    int row0 = blockIdx.y * 128, col0 = blockIdx.x * 128;

    float acc[8][8];
    #pragma unroll
    for (int i = 0; i < 8; i++)
        #pragma unroll
        for (int j = 0; j < 8; j++) acc[i][j] = 0.f;

    for (int k0 = 0; k0 < K; k0 += 16) {
        #pragma unroll
        for (int i = 0; i < 2; i++) {
            int idx = tid + i * 256;
            int ar = idx >> 2, ac = (idx & 3) << 2;
            float4 t = *(const float4*)(Ap + (size_t)(row0 + ar) * K + k0 + ac);
            As[ac + 0][ar] = t.x; As[ac + 1][ar] = t.y;
            As[ac + 2][ar] = t.z; As[ac + 3][ar] = t.w;
        }
        #pragma unroll
        for (int i = 0; i < 2; i++) {
            int idx = tid + i * 256;
            int br = idx >> 5, bc = (idx & 31) << 2;
            *(float4*)(&Bs[br][bc]) =
                *(const float4*)(W + (size_t)(k0 + br) * N + col0 + bc);
        }
        __syncthreads();

        #pragma unroll
        for (int k = 0; k < 16; k++) {
            float a[8], b[8];
            *(float4*)(a)     = *(float4*)&As[k][ty * 8];
            *(float4*)(a + 4) = *(float4*)&As[k][ty * 8 + 4];
            *(float4*)(b)     = *(float4*)&Bs[k][tx * 8];
            *(float4*)(b + 4) = *(float4*)&Bs[k][tx * 8 + 4];
            #pragma unroll
            for (int ii = 0; ii < 8; ii++)
                #pragma unroll
                for (int jj = 0; jj < 8; jj++)
                    acc[ii][jj] = fmaf(a[ii], b[jj], acc[ii][jj]);
        }
        __syncthreads();
    }

    float gr = 0.f, gs = 0.f;
    if (MODE == 1 || MODE == 2) { gr = *grp; gs = *gsp; }

    #pragma unroll
    for (int ii = 0; ii < 8; ii++) {
        int r = row0 + ty * 8 + ii;
        int b = r >> 11, s = r & (S_LEN - 1);
        #pragma unroll
        for (int jj = 0; jj < 8; jj++) {
            int c = col0 + tx * 8 + jj;
            float v = acc[ii][jj];
            if (MODE == 0) {
                v += bias[c];
                if (c < EMB) {
                    int h = c >> 6, d = c & 63;
                    g_q[(((size_t)(b * HEADS + h)) * S_LEN + s) * HDIM + d] = v * 0.125f;
                } else {
                    int c2 = c - EMB;
                    int h = c2 >> 6, d = c2 & 63;
                    g_k[(((size_t)(b * HEADS + h)) * S_LEN + s) * HDIM + d] = v;
                }
            } else if (MODE == 1) {
                float val = gr * v + gs * A[(size_t)r * K + c];
                int h = c >> 6, d = c & 63;
                g_v[(((size_t)(b * HEADS + h)) * S_LEN + s) * HDIM + d] = val;
            } else {
                outp[(size_t)r * N + c] = gr * v + gs * g_ctx[(size_t)r * N + c];
            }
        }
    }
}

// ---------------------------------------------------------------------------
// Flash attention with the extra terms:
//   ctx[q] = g_r * softmax(q K^T) V  +  g_s * v[q]  -  (g_c/(q+1)) * sum_{k<=q} v[k]
// 64x64 tiles, D=64, 256 threads (16x16, 4x4 microtile).
// Q,K stored d-major in smem for conflict-free float4 fragment loads.
// ---------------------------------------------------------------------------
#define NEG_BIG (-1.0e30f)
#define FL_SMEM_FLOATS (64*64 + 64*64 + 64*68 + 64*68 + 4*64)
#define FL_SMEM_BYTES  (FL_SMEM_FLOATS * 4)

__global__ __launch_bounds__(256) void flash_k(
    const float* __restrict__ gr_, const float* __restrict__ gs_,
    const float* __restrict__ gc_)
{
    extern __shared__ float sm[];
    float* Qt   = sm;                 // [64 d][64 r]
    float* Kt   = Qt + 64 * 64;       // [64 d][64 c]
    float* Vs   = Kt + 64 * 64;       // [64 k][68]
    float* Ss   = Vs + 64 * 68;       // [64 r][68]
    float* mrow = Ss + 64 * 68;       // [64]
    float* lrow = mrow + 64;          // [64]
    float* rsc  = lrow + 64;          // [64]
    float* vcol = rsc + 64;           // [64]

    int tid = threadIdx.x;
    int ty = tid >> 4, tx = tid & 15;
    int r0 = ty * 4, c0 = tx * 4;
    int qt = 31 - blockIdx.x;         // big workloads first
    int bh = blockIdx.y;

    const float* Qg = g_q + ((size_t)bh * S_LEN + qt * 64) * HDIM;
    #pragma unroll
    for (int i = 0; i < 4; i++) {
        int idx = tid + i * 256;
        int qr = idx >> 4, qd = (idx & 15) << 2;
        float4 t = *(const float4*)(Qg + qr * 64 + qd);
        Qt[(qd + 0) * 64 + qr] = t.x; Qt[(qd + 1) * 64 + qr] = t.y;
        Qt[(qd + 2) * 64 + qr] = t.z; Qt[(qd + 3) * 64 + qr] = t.w;
    }
    if (tid < 64) { mrow[tid] = NEG_BIG; lrow[tid] = 0.f; }

    float O[4][4]  = {};
    float VS[4][4] = {};

    for (int kt = 0; kt <= qt; kt++) {
        const float* Kg = g_k + ((size_t)bh * S_LEN + kt * 64) * HDIM;
        const float* Vg = g_v + ((size_t)bh * S_LEN + kt * 64) * HDIM;
        #pragma unroll
        for (int i = 0; i < 4; i++) {
            int idx = tid + i * 256;
            int kr = idx >> 4, kd = (idx & 15) << 2;
            float4 t = *(const float4*)(Kg + kr * 64 + kd);
            Kt[(kd + 0) * 64 + kr] = t.x; Kt[(kd + 1) * 64 + kr] = t.y;
            Kt[(kd + 2) * 64 + kr] = t.z; Kt[(kd + 3) * 64 + kr] = t.w;
            float4 u = *(const float4*)(Vg + kr * 64 + kd);
            *(float4*)&Vs[kr * 68 + kd] = u;
        }
        __syncthreads();

        // S = Q K^T  (Q pre-scaled by 1/sqrt(D))
        float s[4][4] = {};
        #pragma unroll 4
        for (int d = 0; d < 64; d++) {
            float4 qv = *(float4*)&Qt[d * 64 + r0];
            float4 kv = *(float4*)&Kt[d * 64 + c0];
            float qa[4] = {qv.x, qv.y, qv.z, qv.w};
            float ka[4] = {kv.x, kv.y, kv.z, kv.w};
            #pragma unroll
            for (int ii = 0; ii < 4; ii++)
                #pragma unroll
                for (int jj = 0; jj < 4; jj++)
                    s[ii][jj] = fmaf(qa[ii], ka[jj], s[ii][jj]);
        }
        if (kt == qt) {
            #pragma unroll
            for (int ii = 0; ii < 4; ii++)
                #pragma unroll
                for (int jj = 0; jj < 4; jj++)
                    if (c0 + jj > r0 + ii) s[ii][jj] = NEG_BIG;
        }
        #pragma unroll
        for (int ii = 0; ii < 4; ii++)
            #pragma unroll
            for (int jj = 0; jj < 4; jj++)
                Ss[(r0 + ii) * 68 + c0 + jj] = s[ii][jj];
        __syncthreads();

        if (tid < 64) {
            // online softmax for one row
            float mo = mrow[tid];
            float mx = mo;
            float* rowp = &Ss[tid * 68];
            for (int j = 0; j < 64; j++) mx = fmaxf(mx, rowp[j]);
            float sc = __expf(mo - mx);
            float l = lrow[tid] * sc;
            for (int j = 0; j < 64; j++) {
                float p = __expf(rowp[j] - mx);
                rowp[j] = p;
                l += p;
            }
            mrow[tid] = mx; lrow[tid] = l; rsc[tid] = sc;
        } else if (tid < 128) {
            int c = tid - 64;
            float t = 0.f;
            for (int kk = 0; kk < 64; kk++) t += Vs[kk * 68 + c];
            vcol[c] = t;
        }
        __syncthreads();

        // rescale O, accumulate P@V
        #pragma unroll
        for (int ii = 0; ii < 4; ii++) {
            float sc = rsc[r0 + ii];
            #pragma unroll
            for (int jj = 0; jj < 4; jj++) O[ii][jj] *= sc;
        }
        for (int kk = 0; kk < 64; kk++) {
            float4 vv = *(float4*)&Vs[kk * 68 + c0];
            float va[4] = {vv.x, vv.y, vv.z, vv.w};
            #pragma unroll
            for (int ii = 0; ii < 4; ii++) {
                float p = Ss[(r0 + ii) * 68 + kk];
                #pragma unroll
                for (int jj = 0; jj < 4; jj++)
                    O[ii][jj] = fmaf(p, va[jj], O[ii][jj]);
            }
        }

        // prefix-sum of V rows (uniform/centre term), unnormalized
        if (kt < qt) {
            #pragma unroll
            for (int ii = 0; ii < 4; ii++)
                #pragma unroll
                for (int jj = 0; jj < 4; jj++)
                    VS[ii][jj] += vcol[c0 + jj];
        } else {
            for (int kk = 0; kk < 64; kk++) {
                float4 vv = *(float4*)&Vs[kk * 68 + c0];
                float va[4] = {vv.x, vv.y, vv.z, vv.w};
                #pragma unroll
                for (int ii = 0; ii < 4; ii++) {
                    if (kk <= r0 + ii) {
                        #pragma unroll
                        for (int jj = 0; jj < 4; jj++) VS[ii][jj] += va[jj];
                    }
                }
            }
        }
        __syncthreads();
    }

    int h = bh & (HEADS - 1), b = bh >> 4;
    float grh = gr_[h], gsh = gs_[h], gch = gc_[h];
    const float* Vq = g_v + ((size_t)bh * S_LEN + qt * 64) * HDIM;
    #pragma unroll
    for (int ii = 0; ii < 4; ii++) {
        int rl = r0 + ii;
        int sidx = qt * 64 + rl;
        float linv = 1.f / lrow[rl];
        float cg = gch / (float)(sidx + 1);
        #pragma unroll
        for (int jj = 0; jj < 4; jj++) {
            int c = c0 + jj;
            float vq = Vq[rl * 64 + c];
            float val = grh * O[ii][jj] * linv + gsh * vq - cg * VS[ii][jj];
            g_ctx[((size_t)(b * S_LEN + sidx)) * EMB + h * HDIM + c] = val;
        }
    }
}

// ---------------------------------------------------------------------------
extern "C" void kernel_launch(void* const* d_in, const int* in_sizes, int n_in,
                              void* d_out, int out_size)
{
    const float* hs   = (const float*)d_in[0];
    const float* qkw  = (const float*)d_in[1];
    const float* qkb  = (const float*)d_in[2];
    const float* vw   = (const float*)d_in[3];
    const float* vrg  = (const float*)d_in[4];
    const float* vsg  = (const float*)d_in[5];
    const float* pw   = (const float*)d_in[6];
    const float* prg  = (const float*)d_in[7];
    const float* psg  = (const float*)d_in[8];
    const float* amr  = (const float*)d_in[9];
    const float* ams  = (const float*)d_in[10];
    const float* cag  = (const float*)d_in[11];
    float* out = (float*)d_out;

    cudaFuncSetAttribute(flash_k, cudaFuncAttributeMaxDynamicSharedMemorySize,
                         FL_SMEM_BYTES);

    dim3 thr(256);
    // QK projection: N=2048
    sgemm_k<0, 2048><<<dim3(2048 / 128, NROWS / 128), thr>>>(
        hs, qkw, qkb, nullptr, nullptr, nullptr);
    // V projection: N=1024
    sgemm_k<1, 1024><<<dim3(1024 / 128, NROWS / 128), thr>>>(
        hs, vw, nullptr, vrg, vsg, nullptr);
    // Flash attention + skip/centre terms
    flash_k<<<dim3(S_LEN / 64, BATCH * HEADS), thr, FL_SMEM_BYTES>>>(amr, ams, cag);
    // Output projection
    sgemm_k<2, 1024><<<dim3(1024 / 128, NROWS / 128), thr>>>(
        nullptr, pw, nullptr, prg, psg, out);
}

// round 6
// speedup vs baseline: 1.1474x; 1.1474x over previous
#include <cuda_runtime.h>
#include <cstdint>
#include <math.h>

#define S_LEN 2048
#define BATCH 2
#define EMB   1024
#define HEADS 16
#define HDIM  64
#define NROWS (BATCH*S_LEN)   // 4096

// Scratch (no allocations allowed)
__device__ float g_q[(size_t)BATCH*HEADS*S_LEN*HDIM];   // [bh][s][d], pre-scaled by 1/sqrt(D)
__device__ float g_k[(size_t)BATCH*HEADS*S_LEN*HDIM];
__device__ float g_v[(size_t)BATCH*HEADS*S_LEN*HDIM];
__device__ float g_ctx[(size_t)NROWS*EMB];              // [b*S+s][e]

// ---------------------------------------------------------------------------
// tf32 helpers (portable PTX, valid under compute_103 target)
// ---------------------------------------------------------------------------
__device__ __forceinline__ uint32_t f2tf32(float x) {
    uint32_t r;
    asm("cvt.rna.tf32.f32 %0, %1;" : "=r"(r) : "f"(x));
    return r;
}
__device__ __forceinline__ void split4(float4 v, uint4& h, uint4& l) {
    h.x = f2tf32(v.x); h.y = f2tf32(v.y); h.z = f2tf32(v.z); h.w = f2tf32(v.w);
    l.x = f2tf32(v.x - __uint_as_float(h.x));
    l.y = f2tf32(v.y - __uint_as_float(h.y));
    l.z = f2tf32(v.z - __uint_as_float(h.z));
    l.w = f2tf32(v.w - __uint_as_float(h.w));
}
// D += A*B, m16n8k8 tf32, row.col
__device__ __forceinline__ void mma8(float* d, const uint32_t* a, const uint32_t* b) {
    asm volatile(
        "mma.sync.aligned.m16n8k8.row.col.f32.tf32.tf32.f32 "
        "{%0,%1,%2,%3}, {%4,%5,%6,%7}, {%8,%9}, {%0,%1,%2,%3};"
        : "+f"(d[0]), "+f"(d[1]), "+f"(d[2]), "+f"(d[3])
        : "r"(a[0]), "r"(a[1]), "r"(a[2]), "r"(a[3]), "r"(b[0]), "r"(b[1]));
}

// ---------------------------------------------------------------------------
// tf32x3 tensor-core GEMM: 128x128 CTA tile, 8 warps (2x4), 64x32 warp tile.
// BK=16, double-buffered smem with PRE-SPLIT hi/lo tf32.
// C = Ah@Bh + Al@Bh + Ah@Bl  (~fp32 accuracy).
// MODE 0: C = X@Wqk + bias -> g_q (*0.125) / g_k   (NDIM=2048)
// MODE 1: v = gr*C + gs*X -> g_v                   (NDIM=1024)
// MODE 2: out = gr*C + gs*ctx -> outp              (NDIM=1024)
// ---------------------------------------------------------------------------
#define ASTRIDE 20      // 128 rows x 20 floats (pad 4): conflict-free frags
#define BSTRIDE 136     // 16 k x 136 floats (pad 8): conflict-free frags
#define ABUF (128*ASTRIDE)   // 2560 floats per buffer
#define BBUF (16*BSTRIDE)    // 2176 floats per buffer
#define GM_SMEM ((2*ABUF*2 + 2*BBUF*2) * 4)   // 75776 bytes

template<int MODE, int NDIM>
__global__ __launch_bounds__(256) void mma_gemm(
    const float* __restrict__ A, const float* __restrict__ W,
    const float* __restrict__ bias,
    const float* __restrict__ grp, const float* __restrict__ gsp,
    float* __restrict__ outp)
{
    constexpr int K = 1024;
    extern __shared__ float sm[];
    float* AsH = sm;                    // [2][128][ASTRIDE]
    float* AsL = AsH + 2 * ABUF;
    float* BsH = AsL + 2 * ABUF;        // [2][16][BSTRIDE]
    float* BsL = BsH + 2 * BBUF;

    const float* Ap = (MODE == 2) ? g_ctx : A;

    int tid = threadIdx.x;
    int wid = tid >> 5, lane = tid & 31;
    int wr = wid >> 2, wc = wid & 3;
    int gid = lane >> 2, tig = lane & 3;
    int row0 = blockIdx.y * 128, col0 = blockIdx.x * 128;

    float acc[4][4][4];
    #pragma unroll
    for (int mt = 0; mt < 4; mt++)
        #pragma unroll
        for (int nt = 0; nt < 4; nt++)
            #pragma unroll
            for (int f = 0; f < 4; f++) acc[mt][nt][f] = 0.f;

    float4 pa[2], pb[2];

    auto ldg = [&](int kc) {
        int k0 = kc * 16;
        #pragma unroll
        for (int i = 0; i < 2; i++) {
            int idx = tid + i * 256;
            pa[i] = *(const float4*)(Ap + (size_t)(row0 + (idx >> 2)) * K + k0 + ((idx & 3) << 2));
            pb[i] = *(const float4*)(W + (size_t)(k0 + (idx >> 5)) * NDIM + col0 + ((idx & 31) << 2));
        }
    };
    auto sts = [&](int buf) {
        #pragma unroll
        for (int i = 0; i < 2; i++) {
            int idx = tid + i * 256;
            {
                int r = idx >> 2, kq = (idx & 3) << 2;
                uint4 h, l; split4(pa[i], h, l);
                *(uint4*)&AsH[buf * ABUF + r * ASTRIDE + kq] = h;
                *(uint4*)&AsL[buf * ABUF + r * ASTRIDE + kq] = l;
            }
            {
                int k = idx >> 5, n = (idx & 31) << 2;
                uint4 h, l; split4(pb[i], h, l);
                *(uint4*)&BsH[buf * BBUF + k * BSTRIDE + n] = h;
                *(uint4*)&BsL[buf * BBUF + k * BSTRIDE + n] = l;
            }
        }
    };

    ldg(0); sts(0);
    __syncthreads();

    for (int kc = 0; kc < 64; kc++) {
        int cb = kc & 1;
        if (kc < 63) ldg(kc + 1);

        #pragma unroll
        for (int k8 = 0; k8 < 2; k8++) {
            int kk = k8 * 8;
            uint32_t ah[4][4], al[4][4], bh[4][2], bl[4][2];
            #pragma unroll
            for (int mt = 0; mt < 4; mt++) {
                int r = wr * 64 + mt * 16 + gid;
                int base = cb * ABUF + r * ASTRIDE + kk + tig;
                ah[mt][0] = __float_as_uint(AsH[base]);
                ah[mt][1] = __float_as_uint(AsH[base + 8 * ASTRIDE]);
                ah[mt][2] = __float_as_uint(AsH[base + 4]);
                ah[mt][3] = __float_as_uint(AsH[base + 8 * ASTRIDE + 4]);
                al[mt][0] = __float_as_uint(AsL[base]);
                al[mt][1] = __float_as_uint(AsL[base + 8 * ASTRIDE]);
                al[mt][2] = __float_as_uint(AsL[base + 4]);
                al[mt][3] = __float_as_uint(AsL[base + 8 * ASTRIDE + 4]);
            }
            #pragma unroll
            for (int nt = 0; nt < 4; nt++) {
                int n = wc * 32 + nt * 8 + gid;
                int base = cb * BBUF + (kk + tig) * BSTRIDE + n;
                bh[nt][0] = __float_as_uint(BsH[base]);
                bh[nt][1] = __float_as_uint(BsH[base + 4 * BSTRIDE]);
                bl[nt][0] = __float_as_uint(BsL[base]);
                bl[nt][1] = __float_as_uint(BsL[base + 4 * BSTRIDE]);
            }
            #pragma unroll
            for (int mt = 0; mt < 4; mt++)
                #pragma unroll
                for (int nt = 0; nt < 4; nt++) {
                    mma8(acc[mt][nt], ah[mt], bh[nt]);
                    mma8(acc[mt][nt], al[mt], bh[nt]);
                    mma8(acc[mt][nt], ah[mt], bl[nt]);
                }
        }

        if (kc < 63) {
            sts((kc + 1) & 1);
            __syncthreads();
        }
    }

    // Epilogue
    float gr = 0.f, gs = 0.f;
    if (MODE == 1 || MODE == 2) { gr = *grp; gs = *gsp; }

    #pragma unroll
    for (int mt = 0; mt < 4; mt++) {
        #pragma unroll
        for (int nt = 0; nt < 4; nt++) {
            int rb = row0 + wr * 64 + mt * 16;
            int cb2 = col0 + wc * 32 + nt * 8;
            #pragma unroll
            for (int half = 0; half < 2; half++) {
                int r = rb + gid + half * 8;
                int b = r >> 11, s = r & (S_LEN - 1);
                #pragma unroll
                for (int e = 0; e < 2; e++) {
                    int c = cb2 + tig * 2 + e;
                    float v = acc[mt][nt][half * 2 + e];
                    if (MODE == 0) {
                        v += bias[c];
                        if (c < EMB) {
                            int h = c >> 6, d = c & 63;
                            g_q[(((size_t)(b * HEADS + h)) * S_LEN + s) * HDIM + d] = v * 0.125f;
                        } else {
                            int c2 = c - EMB;
                            int h = c2 >> 6, d = c2 & 63;
                            g_k[(((size_t)(b * HEADS + h)) * S_LEN + s) * HDIM + d] = v;
                        }
                    } else if (MODE == 1) {
                        int h = c >> 6, d = c & 63;
                        g_v[(((size_t)(b * HEADS + h)) * S_LEN + s) * HDIM + d] =
                            gr * v + gs * A[(size_t)r * K + c];
                    } else {
                        outp[(size_t)r * NDIM + c] =
                            gr * v + gs * g_ctx[(size_t)r * K + c];
                    }
                }
            }
        }
    }
}

// ---------------------------------------------------------------------------
// Flash attention with the extra terms (unchanged, known-good):
//   ctx[q] = g_r * softmax(q K^T) V  +  g_s * v[q]  -  (g_c/(q+1)) * sum_{k<=q} v[k]
// ---------------------------------------------------------------------------
#define NEG_BIG (-1.0e30f)
#define FL_SMEM_FLOATS (64*64 + 64*64 + 64*68 + 64*68 + 4*64)
#define FL_SMEM_BYTES  (FL_SMEM_FLOATS * 4)

__global__ __launch_bounds__(256) void flash_k(
    const float* __restrict__ gr_, const float* __restrict__ gs_,
    const float* __restrict__ gc_)
{
    extern __shared__ float sm[];
    float* Qt   = sm;                 // [64 d][64 r]
    float* Kt   = Qt + 64 * 64;       // [64 d][64 c]
    float* Vs   = Kt + 64 * 64;       // [64 k][68]
    float* Ss   = Vs + 64 * 68;       // [64 r][68]
    float* mrow = Ss + 64 * 68;       // [64]
    float* lrow = mrow + 64;          // [64]
    float* rsc  = lrow + 64;          // [64]
    float* vcol = rsc + 64;           // [64]

    int tid = threadIdx.x;
    int ty = tid >> 4, tx = tid & 15;
    int r0 = ty * 4, c0 = tx * 4;
    int qt = 31 - blockIdx.x;         // big workloads first
    int bh = blockIdx.y;

    const float* Qg = g_q + ((size_t)bh * S_LEN + qt * 64) * HDIM;
    #pragma unroll
    for (int i = 0; i < 4; i++) {
        int idx = tid + i * 256;
        int qr = idx >> 4, qd = (idx & 15) << 2;
        float4 t = *(const float4*)(Qg + qr * 64 + qd);
        Qt[(qd + 0) * 64 + qr] = t.x; Qt[(qd + 1) * 64 + qr] = t.y;
        Qt[(qd + 2) * 64 + qr] = t.z; Qt[(qd + 3) * 64 + qr] = t.w;
    }
    if (tid < 64) { mrow[tid] = NEG_BIG; lrow[tid] = 0.f; }

    float O[4][4]  = {};
    float VS[4][4] = {};

    for (int kt = 0; kt <= qt; kt++) {
        const float* Kg = g_k + ((size_t)bh * S_LEN + kt * 64) * HDIM;
        const float* Vg = g_v + ((size_t)bh * S_LEN + kt * 64) * HDIM;
        #pragma unroll
        for (int i = 0; i < 4; i++) {
            int idx = tid + i * 256;
            int kr = idx >> 4, kd = (idx & 15) << 2;
            float4 t = *(const float4*)(Kg + kr * 64 + kd);
            Kt[(kd + 0) * 64 + kr] = t.x; Kt[(kd + 1) * 64 + kr] = t.y;
            Kt[(kd + 2) * 64 + kr] = t.z; Kt[(kd + 3) * 64 + kr] = t.w;
            float4 u = *(const float4*)(Vg + kr * 64 + kd);
            *(float4*)&Vs[kr * 68 + kd] = u;
        }
        __syncthreads();

        float s[4][4] = {};
        #pragma unroll 4
        for (int d = 0; d < 64; d++) {
            float4 qv = *(float4*)&Qt[d * 64 + r0];
            float4 kv = *(float4*)&Kt[d * 64 + c0];
            float qa[4] = {qv.x, qv.y, qv.z, qv.w};
            float ka[4] = {kv.x, kv.y, kv.z, kv.w};
            #pragma unroll
            for (int ii = 0; ii < 4; ii++)
                #pragma unroll
                for (int jj = 0; jj < 4; jj++)
                    s[ii][jj] = fmaf(qa[ii], ka[jj], s[ii][jj]);
        }
        if (kt == qt) {
            #pragma unroll
            for (int ii = 0; ii < 4; ii++)
                #pragma unroll
                for (int jj = 0; jj < 4; jj++)
                    if (c0 + jj > r0 + ii) s[ii][jj] = NEG_BIG;
        }
        #pragma unroll
        for (int ii = 0; ii < 4; ii++)
            #pragma unroll
            for (int jj = 0; jj < 4; jj++)
                Ss[(r0 + ii) * 68 + c0 + jj] = s[ii][jj];
        __syncthreads();

        if (tid < 64) {
            float mo = mrow[tid];
            float mx = mo;
            float* rowp = &Ss[tid * 68];
            for (int j = 0; j < 64; j++) mx = fmaxf(mx, rowp[j]);
            float sc = __expf(mo - mx);
            float l = lrow[tid] * sc;
            for (int j = 0; j < 64; j++) {
                float p = __expf(rowp[j] - mx);
                rowp[j] = p;
                l += p;
            }
            mrow[tid] = mx; lrow[tid] = l; rsc[tid] = sc;
        } else if (tid < 128) {
            int c = tid - 64;
            float t = 0.f;
            for (int kk = 0; kk < 64; kk++) t += Vs[kk * 68 + c];
            vcol[c] = t;
        }
        __syncthreads();

        #pragma unroll
        for (int ii = 0; ii < 4; ii++) {
            float sc = rsc[r0 + ii];
            #pragma unroll
            for (int jj = 0; jj < 4; jj++) O[ii][jj] *= sc;
        }
        for (int kk = 0; kk < 64; kk++) {
            float4 vv = *(float4*)&Vs[kk * 68 + c0];
            float va[4] = {vv.x, vv.y, vv.z, vv.w};
            #pragma unroll
            for (int ii = 0; ii < 4; ii++) {
                float p = Ss[(r0 + ii) * 68 + kk];
                #pragma unroll
                for (int jj = 0; jj < 4; jj++)
                    O[ii][jj] = fmaf(p, va[jj], O[ii][jj]);
            }
        }

        if (kt < qt) {
            #pragma unroll
            for (int ii = 0; ii < 4; ii++)
                #pragma unroll
                for (int jj = 0; jj < 4; jj++)
                    VS[ii][jj] += vcol[c0 + jj];
        } else {
            for (int kk = 0; kk < 64; kk++) {
                float4 vv = *(float4*)&Vs[kk * 68 + c0];
                float va[4] = {vv.x, vv.y, vv.z, vv.w};
                #pragma unroll
                for (int ii = 0; ii < 4; ii++) {
                    if (kk <= r0 + ii) {
                        #pragma unroll
                        for (int jj = 0; jj < 4; jj++) VS[ii][jj] += va[jj];
                    }
                }
            }
        }
        __syncthreads();
    }

    int h = bh & (HEADS - 1), b = bh >> 4;
    float grh = gr_[h], gsh = gs_[h], gch = gc_[h];
    const float* Vq = g_v + ((size_t)bh * S_LEN + qt * 64) * HDIM;
    #pragma unroll
    for (int ii = 0; ii < 4; ii++) {
        int rl = r0 + ii;
        int sidx = qt * 64 + rl;
        float linv = 1.f / lrow[rl];
        float cg = gch / (float)(sidx + 1);
        #pragma unroll
        for (int jj = 0; jj < 4; jj++) {
            int c = c0 + jj;
            float vq = Vq[rl * 64 + c];
            float val = grh * O[ii][jj] * linv + gsh * vq - cg * VS[ii][jj];
            g_ctx[((size_t)(b * S_LEN + sidx)) * EMB + h * HDIM + c] = val;
        }
    }
}

// ---------------------------------------------------------------------------
extern "C" void kernel_launch(void* const* d_in, const int* in_sizes, int n_in,
                              void* d_out, int out_size)
{
    const float* hs   = (const float*)d_in[0];
    const float* qkw  = (const float*)d_in[1];
    const float* qkb  = (const float*)d_in[2];
    const float* vw   = (const float*)d_in[3];
    const float* vrg  = (const float*)d_in[4];
    const float* vsg  = (const float*)d_in[5];
    const float* pw   = (const float*)d_in[6];
    const float* prg  = (const float*)d_in[7];
    const float* psg  = (const float*)d_in[8];
    const float* amr  = (const float*)d_in[9];
    const float* ams  = (const float*)d_in[10];
    const float* cag  = (const float*)d_in[11];
    float* out = (float*)d_out;

    cudaFuncSetAttribute(mma_gemm<0, 2048>, cudaFuncAttributeMaxDynamicSharedMemorySize, GM_SMEM);
    cudaFuncSetAttribute(mma_gemm<1, 1024>, cudaFuncAttributeMaxDynamicSharedMemorySize, GM_SMEM);
    cudaFuncSetAttribute(mma_gemm<2, 1024>, cudaFuncAttributeMaxDynamicSharedMemorySize, GM_SMEM);
    cudaFuncSetAttribute(flash_k, cudaFuncAttributeMaxDynamicSharedMemorySize, FL_SMEM_BYTES);

    dim3 thr(256);
    // QK projection: N=2048
    mma_gemm<0, 2048><<<dim3(2048 / 128, NROWS / 128), thr, GM_SMEM>>>(
        hs, qkw, qkb, nullptr, nullptr, nullptr);
    // V projection: N=1024
    mma_gemm<1, 1024><<<dim3(1024 / 128, NROWS / 128), thr, GM_SMEM>>>(
        hs, vw, nullptr, vrg, vsg, nullptr);
    // Flash attention + skip/centre terms
    flash_k<<<dim3(S_LEN / 64, BATCH * HEADS), thr, FL_SMEM_BYTES>>>(amr, ams, cag);
    // Output projection
    mma_gemm<2, 1024><<<dim3(1024 / 128, NROWS / 128), thr, GM_SMEM>>>(
        nullptr, pw, nullptr, prg, psg, out);
}

// round 7
// speedup vs baseline: 1.3659x; 1.1905x over previous
#include <cuda_runtime.h>
#include <cstdint>
#include <math.h>

#define S_LEN 2048
#define BATCH 2
#define EMB   1024
#define HEADS 16
#define HDIM  64
#define NROWS (BATCH*S_LEN)   // 4096

// Scratch (no allocations allowed)
__device__ float g_q[(size_t)BATCH*HEADS*S_LEN*HDIM];   // [bh][s][d], pre-scaled by 1/sqrt(D)
__device__ float g_k[(size_t)BATCH*HEADS*S_LEN*HDIM];
__device__ float g_v[(size_t)BATCH*HEADS*S_LEN*HDIM];
__device__ float g_vs[(size_t)BATCH*HEADS*S_LEN*HDIM];  // inclusive prefix sums of V over s
__device__ float g_segsum[BATCH*HEADS*8*HDIM];
__device__ float g_ctx[(size_t)NROWS*EMB];              // [b*S+s][e]

// ---------------------------------------------------------------------------
// tf32 helpers (portable PTX, valid under compute_103 target)
// ---------------------------------------------------------------------------
__device__ __forceinline__ uint32_t f2tf32(float x) {
    uint32_t r;
    asm("cvt.rna.tf32.f32 %0, %1;" : "=r"(r) : "f"(x));
    return r;
}
__device__ __forceinline__ void split4(float4 v, uint4& h, uint4& l) {
    h.x = f2tf32(v.x); h.y = f2tf32(v.y); h.z = f2tf32(v.z); h.w = f2tf32(v.w);
    l.x = f2tf32(v.x - __uint_as_float(h.x));
    l.y = f2tf32(v.y - __uint_as_float(h.y));
    l.z = f2tf32(v.z - __uint_as_float(h.z));
    l.w = f2tf32(v.w - __uint_as_float(h.w));
}
// D += A*B, m16n8k8 tf32, row.col
__device__ __forceinline__ void mma8(float* d, const uint32_t* a, const uint32_t* b) {
    asm volatile(
        "mma.sync.aligned.m16n8k8.row.col.f32.tf32.tf32.f32 "
        "{%0,%1,%2,%3}, {%4,%5,%6,%7}, {%8,%9}, {%0,%1,%2,%3};"
        : "+f"(d[0]), "+f"(d[1]), "+f"(d[2]), "+f"(d[3])
        : "r"(a[0]), "r"(a[1]), "r"(a[2]), "r"(a[3]), "r"(b[0]), "r"(b[1]));
}

// Fast exp for x <= 0 on FMA/ALU pipes (avoids MUFU serialization).
// exp(x) = 2^(x*log2e); deg-5 Taylor of 2^f on [-0.5,0.5], rel err ~2.4e-6.
__device__ __forceinline__ float fexp(float x) {
    float y = x * 1.4426950408889634f;
    y = fmaxf(y, -126.0f);
    float rn = y + 12582912.0f;                  // round-to-nearest magic
    int   n  = __float_as_int(rn) - 0x4B400000;
    float f  = y - (rn - 12582912.0f);
    float p = 1.3333558146e-3f;
    p = fmaf(p, f, 9.6181291076e-3f);
    p = fmaf(p, f, 5.5504108664e-2f);
    p = fmaf(p, f, 2.4022650695910072e-1f);
    p = fmaf(p, f, 6.9314718055994531e-1f);
    p = fmaf(p, f, 1.0f);
    return __int_as_float(__float_as_int(p) + (n << 23));
}

// ---------------------------------------------------------------------------
// tf32x3 tensor-core GEMM (unchanged from round 6, works): 128x128 CTA tile.
// ---------------------------------------------------------------------------
#define ASTRIDE 20
#define BSTRIDE 136
#define ABUF (128*ASTRIDE)
#define BBUF (16*BSTRIDE)
#define GM_SMEM ((2*ABUF*2 + 2*BBUF*2) * 4)

template<int MODE, int NDIM>
__global__ __launch_bounds__(256) void mma_gemm(
    const float* __restrict__ A, const float* __restrict__ W,
    const float* __restrict__ bias,
    const float* __restrict__ grp, const float* __restrict__ gsp,
    float* __restrict__ outp)
{
    constexpr int K = 1024;
    extern __shared__ float sm[];
    float* AsH = sm;
    float* AsL = AsH + 2 * ABUF;
    float* BsH = AsL + 2 * ABUF;
    float* BsL = BsH + 2 * BBUF;

    const float* Ap = (MODE == 2) ? g_ctx : A;

    int tid = threadIdx.x;
    int wid = tid >> 5, lane = tid & 31;
    int wr = wid >> 2, wc = wid & 3;
    int gid = lane >> 2, tig = lane & 3;
    int row0 = blockIdx.y * 128, col0 = blockIdx.x * 128;

    float acc[4][4][4];
    #pragma unroll
    for (int mt = 0; mt < 4; mt++)
        #pragma unroll
        for (int nt = 0; nt < 4; nt++)
            #pragma unroll
            for (int f = 0; f < 4; f++) acc[mt][nt][f] = 0.f;

    float4 pa[2], pb[2];

    auto ldg = [&](int kc) {
        int k0 = kc * 16;
        #pragma unroll
        for (int i = 0; i < 2; i++) {
            int idx = tid + i * 256;
            pa[i] = *(const float4*)(Ap + (size_t)(row0 + (idx >> 2)) * K + k0 + ((idx & 3) << 2));
            pb[i] = *(const float4*)(W + (size_t)(k0 + (idx >> 5)) * NDIM + col0 + ((idx & 31) << 2));
        }
    };
    auto sts = [&](int buf) {
        #pragma unroll
        for (int i = 0; i < 2; i++) {
            int idx = tid + i * 256;
            {
                int r = idx >> 2, kq = (idx & 3) << 2;
                uint4 h, l; split4(pa[i], h, l);
                *(uint4*)&AsH[buf * ABUF + r * ASTRIDE + kq] = h;
                *(uint4*)&AsL[buf * ABUF + r * ASTRIDE + kq] = l;
            }
            {
                int k = idx >> 5, n = (idx & 31) << 2;
                uint4 h, l; split4(pb[i], h, l);
                *(uint4*)&BsH[buf * BBUF + k * BSTRIDE + n] = h;
                *(uint4*)&BsL[buf * BBUF + k * BSTRIDE + n] = l;
            }
        }
    };

    ldg(0); sts(0);
    __syncthreads();

    for (int kc = 0; kc < 64; kc++) {
        int cb = kc & 1;
        if (kc < 63) ldg(kc + 1);

        #pragma unroll
        for (int k8 = 0; k8 < 2; k8++) {
            int kk = k8 * 8;
            uint32_t ah[4][4], al[4][4], bh[4][2], bl[4][2];
            #pragma unroll
            for (int mt = 0; mt < 4; mt++) {
                int r = wr * 64 + mt * 16 + gid;
                int base = cb * ABUF + r * ASTRIDE + kk + tig;
                ah[mt][0] = __float_as_uint(AsH[base]);
                ah[mt][1] = __float_as_uint(AsH[base + 8 * ASTRIDE]);
                ah[mt][2] = __float_as_uint(AsH[base + 4]);
                ah[mt][3] = __float_as_uint(AsH[base + 8 * ASTRIDE + 4]);
                al[mt][0] = __float_as_uint(AsL[base]);
                al[mt][1] = __float_as_uint(AsL[base + 8 * ASTRIDE]);
                al[mt][2] = __float_as_uint(AsL[base + 4]);
                al[mt][3] = __float_as_uint(AsL[base + 8 * ASTRIDE + 4]);
            }
            #pragma unroll
            for (int nt = 0; nt < 4; nt++) {
                int n = wc * 32 + nt * 8 + gid;
                int base = cb * BBUF + (kk + tig) * BSTRIDE + n;
                bh[nt][0] = __float_as_uint(BsH[base]);
                bh[nt][1] = __float_as_uint(BsH[base + 4 * BSTRIDE]);
                bl[nt][0] = __float_as_uint(BsL[base]);
                bl[nt][1] = __float_as_uint(BsL[base + 4 * BSTRIDE]);
            }
            #pragma unroll
            for (int mt = 0; mt < 4; mt++)
                #pragma unroll
                for (int nt = 0; nt < 4; nt++) {
                    mma8(acc[mt][nt], ah[mt], bh[nt]);
                    mma8(acc[mt][nt], al[mt], bh[nt]);
                    mma8(acc[mt][nt], ah[mt], bl[nt]);
                }
        }

        if (kc < 63) {
            sts((kc + 1) & 1);
            __syncthreads();
        }
    }

    float gr = 0.f, gs = 0.f;
    if (MODE == 1 || MODE == 2) { gr = *grp; gs = *gsp; }

    #pragma unroll
    for (int mt = 0; mt < 4; mt++) {
        #pragma unroll
        for (int nt = 0; nt < 4; nt++) {
            int rb = row0 + wr * 64 + mt * 16;
            int cb2 = col0 + wc * 32 + nt * 8;
            #pragma unroll
            for (int half = 0; half < 2; half++) {
                int r = rb + gid + half * 8;
                int b = r >> 11, s = r & (S_LEN - 1);
                #pragma unroll
                for (int e = 0; e < 2; e++) {
                    int c = cb2 + tig * 2 + e;
                    float v = acc[mt][nt][half * 2 + e];
                    if (MODE == 0) {
                        v += bias[c];
                        if (c < EMB) {
                            int h = c >> 6, d = c & 63;
                            g_q[(((size_t)(b * HEADS + h)) * S_LEN + s) * HDIM + d] = v * 0.125f;
                        } else {
                            int c2 = c - EMB;
                            int h = c2 >> 6, d = c2 & 63;
                            g_k[(((size_t)(b * HEADS + h)) * S_LEN + s) * HDIM + d] = v;
                        }
                    } else if (MODE == 1) {
                        int h = c >> 6, d = c & 63;
                        g_v[(((size_t)(b * HEADS + h)) * S_LEN + s) * HDIM + d] =
                            gr * v + gs * A[(size_t)r * K + c];
                    } else {
                        outp[(size_t)r * NDIM + c] =
                            gr * v + gs * g_ctx[(size_t)r * K + c];
                    }
                }
            }
        }
    }
}

// ---------------------------------------------------------------------------
// V prefix sums (two passes): g_vs[bh][s][d] = sum_{k<=s} g_v[bh][k][d]
// ---------------------------------------------------------------------------
__global__ __launch_bounds__(64) void vseg_k() {
    int bh = blockIdx.x >> 3, seg = blockIdx.x & 7, d = threadIdx.x;
    const float* vp = g_v + ((size_t)bh * S_LEN + seg * 256) * 64 + d;
    float acc = 0.f;
    #pragma unroll 8
    for (int s = 0; s < 256; s++) acc += vp[(size_t)s * 64];
    g_segsum[(bh * 8 + seg) * 64 + d] = acc;
}
__global__ __launch_bounds__(64) void vprefix_k() {
    int bh = blockIdx.x >> 3, seg = blockIdx.x & 7, d = threadIdx.x;
    float acc = 0.f;
    for (int t = 0; t < seg; t++) acc += g_segsum[(bh * 8 + t) * 64 + d];
    const float* vp = g_v + ((size_t)bh * S_LEN + seg * 256) * 64 + d;
    float* op = g_vs + ((size_t)bh * S_LEN + seg * 256) * 64 + d;
    #pragma unroll 8
    for (int s = 0; s < 256; s++) { acc += vp[(size_t)s * 64]; op[(size_t)s * 64] = acc; }
}

// ---------------------------------------------------------------------------
// Tensor-core flash attention (tf32x3):
//   ctx[q] = g_r*softmax(qK^T)V + g_s*v[q] - (g_c/(q+1))*VS[q]
// 128 q-rows/CTA, 64-wide k-tiles, 8 warps. Warp w owns rows {w*8..w*8+7}
// and {64+w*8..64+w*8+7} (fragment halves). Q frags in regs; K transposed +
// V natural in smem as interleaved {hi,lo} tf32 pairs, double-buffered.
// P round-trips via warp-private smem.
// ---------------------------------------------------------------------------
#define KTSTR 136                       // floats per row ({hi,lo} x 64 + pad)
#define KTBUF (64*KTSTR)                // 8704 floats
#define FL2_SMEM ((2*KTBUF + 2*KTBUF + 128*KTSTR) * 4)   // 208896 B
#define NEG_BIG (-1.0e30f)

__global__ __launch_bounds__(256) void flash_mma(
    const float* __restrict__ gr_, const float* __restrict__ gs_,
    const float* __restrict__ gc_)
{
    extern __shared__ float smf[];
    float* KTb = smf;                    // [2][64 d][KTSTR]  (K transposed)
    float* VTb = smf + 2 * KTBUF;        // [2][64 k][KTSTR]  (V natural)
    float* PT  = smf + 4 * KTBUF;        // [128 q][KTSTR]

    int tid = threadIdx.x, wid = tid >> 5, lane = tid & 31;
    int gid = lane >> 2, tig = lane & 3;
    int qt = 15 - (int)blockIdx.x;       // big workloads first
    int bh = blockIdx.y;
    int qbase = qt * 128;
    int rAp = wid * 8 + gid, rBp = 64 + wid * 8 + gid;
    int qA = qbase + rAp, qB = qbase + rBp;

    // Q fragments (hi/lo) resident in registers
    uint32_t qh[8][4], ql[8][4];
    {
        const float* Qp = g_q + (size_t)bh * S_LEN * 64;
        #pragma unroll
        for (int k8 = 0; k8 < 8; k8++) {
            float v[4];
            v[0] = Qp[(size_t)qA * 64 + k8 * 8 + tig];
            v[1] = Qp[(size_t)qB * 64 + k8 * 8 + tig];
            v[2] = Qp[(size_t)qA * 64 + k8 * 8 + tig + 4];
            v[3] = Qp[(size_t)qB * 64 + k8 * 8 + tig + 4];
            #pragma unroll
            for (int j = 0; j < 4; j++) {
                qh[k8][j] = f2tf32(v[j]);
                ql[k8][j] = f2tf32(v[j] - __uint_as_float(qh[k8][j]));
            }
        }
    }

    float O[8][4];
    #pragma unroll
    for (int nf = 0; nf < 8; nf++)
        #pragma unroll
        for (int f = 0; f < 4; f++) O[nf][f] = 0.f;
    float mA = NEG_BIG, mB = NEG_BIG, lA = 0.f, lB = 0.f;

    const int kmax = 2 * qt + 2;

    float  kst[16];
    float4 vst[4];
    auto ldgKV = [&](int kt) {
        const float* Kg = g_k + ((size_t)bh * S_LEN + kt * 64) * 64;
        const float* Vg = g_v + ((size_t)bh * S_LEN + kt * 64) * 64;
        #pragma unroll
        for (int i = 0; i < 4; i++) {
            int idx = tid + i * 256;
            int d = idx & 63, kp4 = (idx >> 6) << 2;
            #pragma unroll
            for (int j = 0; j < 4; j++)
                kst[i * 4 + j] = Kg[(size_t)(kp4 + j) * 64 + d];
            int vk = idx >> 4, d4 = (idx & 15) << 2;
            vst[i] = *(const float4*)(Vg + (size_t)vk * 64 + d4);
        }
    };
    auto stsKV = [&](int buf) {
        float* kb0 = KTb + buf * KTBUF;
        float* vb0 = VTb + buf * KTBUF;
        #pragma unroll
        for (int i = 0; i < 4; i++) {
            int idx = tid + i * 256;
            int d = idx & 63, kp4 = (idx >> 6) << 2;
            float4 kv = make_float4(kst[i*4], kst[i*4+1], kst[i*4+2], kst[i*4+3]);
            uint4 kh, kl; split4(kv, kh, kl);
            float* kp = kb0 + d * KTSTR + kp4 * 2;
            *(float4*)kp = make_float4(__uint_as_float(kh.x), __uint_as_float(kl.x),
                                       __uint_as_float(kh.y), __uint_as_float(kl.y));
            *(float4*)(kp + 4) = make_float4(__uint_as_float(kh.z), __uint_as_float(kl.z),
                                             __uint_as_float(kh.w), __uint_as_float(kl.w));
            int vk = idx >> 4, d4 = (idx & 15) << 2;
            uint4 vh, vl; split4(vst[i], vh, vl);
            float* vp = vb0 + vk * KTSTR + d4 * 2;
            *(float4*)vp = make_float4(__uint_as_float(vh.x), __uint_as_float(vl.x),
                                       __uint_as_float(vh.y), __uint_as_float(vl.y));
            *(float4*)(vp + 4) = make_float4(__uint_as_float(vh.z), __uint_as_float(vl.z),
                                             __uint_as_float(vh.w), __uint_as_float(vl.w));
        }
    };

    ldgKV(0); stsKV(0);
    __syncthreads();

    for (int kt = 0; kt < kmax; kt++) {
        int buf = kt & 1;

        // S = Q @ K^T  (tf32x3)
        float sacc[8][4];
        #pragma unroll
        for (int nf = 0; nf < 8; nf++)
            #pragma unroll
            for (int f = 0; f < 4; f++) sacc[nf][f] = 0.f;
        {
            const float* kb = KTb + buf * KTBUF;
            #pragma unroll
            for (int k8 = 0; k8 < 8; k8++) {
                #pragma unroll
                for (int nf = 0; nf < 8; nf++) {
                    float2 b0 = *(const float2*)(kb + (k8*8 + tig) * KTSTR + (nf*8 + gid) * 2);
                    float2 b1 = *(const float2*)(kb + (k8*8 + tig + 4) * KTSTR + (nf*8 + gid) * 2);
                    uint32_t bhv[2] = {__float_as_uint(b0.x), __float_as_uint(b1.x)};
                    uint32_t blv[2] = {__float_as_uint(b0.y), __float_as_uint(b1.y)};
                    mma8(sacc[nf], qh[k8], bhv);
                    mma8(sacc[nf], ql[k8], bhv);
                    mma8(sacc[nf], qh[k8], blv);
                }
            }
        }

        if (kt + 1 < kmax) ldgKV(kt + 1);

        // causal mask (only last two tiles can cross the diagonal)
        if (kt >= 2 * qt) {
            int c0g = kt * 64;
            #pragma unroll
            for (int nf = 0; nf < 8; nf++)
                #pragma unroll
                for (int e = 0; e < 2; e++) {
                    int col = c0g + nf * 8 + tig * 2 + e;
                    if (col > qA) sacc[nf][e]     = NEG_BIG;
                    if (col > qB) sacc[nf][2 + e] = NEG_BIG;
                }
        }

        // online softmax (per-thread 2 rows, reduce across tig lanes)
        float mxA = NEG_BIG, mxB = NEG_BIG;
        #pragma unroll
        for (int nf = 0; nf < 8; nf++) {
            mxA = fmaxf(mxA, fmaxf(sacc[nf][0], sacc[nf][1]));
            mxB = fmaxf(mxB, fmaxf(sacc[nf][2], sacc[nf][3]));
        }
        mxA = fmaxf(mxA, __shfl_xor_sync(0xffffffffu, mxA, 1));
        mxA = fmaxf(mxA, __shfl_xor_sync(0xffffffffu, mxA, 2));
        mxB = fmaxf(mxB, __shfl_xor_sync(0xffffffffu, mxB, 1));
        mxB = fmaxf(mxB, __shfl_xor_sync(0xffffffffu, mxB, 2));
        float mnA = fmaxf(mA, mxA), mnB = fmaxf(mB, mxB);
        float scA = fexp(mA - mnA), scB = fexp(mB - mnB);
        mA = mnA; mB = mnB;
        float sumA = 0.f, sumB = 0.f;
        #pragma unroll
        for (int nf = 0; nf < 8; nf++) {
            float p0 = fexp(sacc[nf][0] - mnA);
            float p1 = fexp(sacc[nf][1] - mnA);
            float p2 = fexp(sacc[nf][2] - mnB);
            float p3 = fexp(sacc[nf][3] - mnB);
            sumA += p0 + p1; sumB += p2 + p3;
            uint32_t h0 = f2tf32(p0), h1 = f2tf32(p1), h2 = f2tf32(p2), h3 = f2tf32(p3);
            uint32_t l0 = f2tf32(p0 - __uint_as_float(h0));
            uint32_t l1 = f2tf32(p1 - __uint_as_float(h1));
            uint32_t l2 = f2tf32(p2 - __uint_as_float(h2));
            uint32_t l3 = f2tf32(p3 - __uint_as_float(h3));
            int colo = (nf * 8 + tig * 2) * 2;
            *(float4*)(PT + rAp * KTSTR + colo) =
                make_float4(__uint_as_float(h0), __uint_as_float(l0),
                            __uint_as_float(h1), __uint_as_float(l1));
            *(float4*)(PT + rBp * KTSTR + colo) =
                make_float4(__uint_as_float(h2), __uint_as_float(l2),
                            __uint_as_float(h3), __uint_as_float(l3));
        }
        sumA += __shfl_xor_sync(0xffffffffu, sumA, 1);
        sumA += __shfl_xor_sync(0xffffffffu, sumA, 2);
        sumB += __shfl_xor_sync(0xffffffffu, sumB, 1);
        sumB += __shfl_xor_sync(0xffffffffu, sumB, 2);
        lA = lA * scA + sumA;
        lB = lB * scB + sumB;
        #pragma unroll
        for (int nf = 0; nf < 8; nf++) {
            O[nf][0] *= scA; O[nf][1] *= scA;
            O[nf][2] *= scB; O[nf][3] *= scB;
        }
        __syncwarp();

        if (kt + 1 < kmax) stsKV((kt + 1) & 1);

        // O += P @ V  (tf32x3)
        {
            const float* vb = VTb + buf * KTBUF;
            #pragma unroll
            for (int k8 = 0; k8 < 8; k8++) {
                float2 a0 = *(const float2*)(PT + rAp * KTSTR + (k8*8 + tig) * 2);
                float2 a1 = *(const float2*)(PT + rBp * KTSTR + (k8*8 + tig) * 2);
                float2 a2 = *(const float2*)(PT + rAp * KTSTR + (k8*8 + tig + 4) * 2);
                float2 a3 = *(const float2*)(PT + rBp * KTSTR + (k8*8 + tig + 4) * 2);
                uint32_t ah[4] = {__float_as_uint(a0.x), __float_as_uint(a1.x),
                                  __float_as_uint(a2.x), __float_as_uint(a3.x)};
                uint32_t al[4] = {__float_as_uint(a0.y), __float_as_uint(a1.y),
                                  __float_as_uint(a2.y), __float_as_uint(a3.y)};
                #pragma unroll
                for (int nf = 0; nf < 8; nf++) {
                    float2 b0 = *(const float2*)(vb + (k8*8 + tig) * KTSTR + (nf*8 + gid) * 2);
                    float2 b1 = *(const float2*)(vb + (k8*8 + tig + 4) * KTSTR + (nf*8 + gid) * 2);
                    uint32_t bhv[2] = {__float_as_uint(b0.x), __float_as_uint(b1.x)};
                    uint32_t blv[2] = {__float_as_uint(b0.y), __float_as_uint(b1.y)};
                    mma8(O[nf], ah, bhv);
                    mma8(O[nf], al, bhv);
                    mma8(O[nf], ah, blv);
                }
            }
        }
        __syncthreads();
    }

    // Epilogue
    int h = bh & (HEADS - 1), b = bh >> 4;
    float grh = gr_[h], gsh = gs_[h], gch = gc_[h];
    float giA = grh / lA, giB = grh / lB;
    float cgA = gch / (float)(qA + 1), cgB = gch / (float)(qB + 1);
    const float* vrA  = g_v  + ((size_t)bh * S_LEN + qA) * 64;
    const float* vrB  = g_v  + ((size_t)bh * S_LEN + qB) * 64;
    const float* vsA  = g_vs + ((size_t)bh * S_LEN + qA) * 64;
    const float* vsB  = g_vs + ((size_t)bh * S_LEN + qB) * 64;
    float* oA = g_ctx + ((size_t)(b * S_LEN + qA)) * EMB + h * 64;
    float* oB = g_ctx + ((size_t)(b * S_LEN + qB)) * EMB + h * 64;
    #pragma unroll
    for (int nf = 0; nf < 8; nf++) {
        int d0 = nf * 8 + tig * 2;
        float2 vqA = *(const float2*)(vrA + d0);
        float2 vqB = *(const float2*)(vrB + d0);
        float2 psA = *(const float2*)(vsA + d0);
        float2 psB = *(const float2*)(vsB + d0);
        float2 ra, rb;
        ra.x = O[nf][0] * giA + gsh * vqA.x - cgA * psA.x;
        ra.y = O[nf][1] * giA + gsh * vqA.y - cgA * psA.y;
        rb.x = O[nf][2] * giB + gsh * vqB.x - cgB * psB.x;
        rb.y = O[nf][3] * giB + gsh * vqB.y - cgB * psB.y;
        *(float2*)(oA + d0) = ra;
        *(float2*)(oB + d0) = rb;
    }
}

// ---------------------------------------------------------------------------
extern "C" void kernel_launch(void* const* d_in, const int* in_sizes, int n_in,
                              void* d_out, int out_size)
{
    const float* hs   = (const float*)d_in[0];
    const float* qkw  = (const float*)d_in[1];
    const float* qkb  = (const float*)d_in[2];
    const float* vw   = (const float*)d_in[3];
    const float* vrg  = (const float*)d_in[4];
    const float* vsg  = (const float*)d_in[5];
    const float* pw   = (const float*)d_in[6];
    const float* prg  = (const float*)d_in[7];
    const float* psg  = (const float*)d_in[8];
    const float* amr  = (const float*)d_in[9];
    const float* ams  = (const float*)d_in[10];
    const float* cag  = (const float*)d_in[11];
    float* out = (float*)d_out;

    cudaFuncSetAttribute(mma_gemm<0, 2048>, cudaFuncAttributeMaxDynamicSharedMemorySize, GM_SMEM);
    cudaFuncSetAttribute(mma_gemm<1, 1024>, cudaFuncAttributeMaxDynamicSharedMemorySize, GM_SMEM);
    cudaFuncSetAttribute(mma_gemm<2, 1024>, cudaFuncAttributeMaxDynamicSharedMemorySize, GM_SMEM);
    cudaFuncSetAttribute(flash_mma, cudaFuncAttributeMaxDynamicSharedMemorySize, FL2_SMEM);

    dim3 thr(256);
    // QK projection
    mma_gemm<0, 2048><<<dim3(2048 / 128, NROWS / 128), thr, GM_SMEM>>>(
        hs, qkw, qkb, nullptr, nullptr, nullptr);
    // V projection
    mma_gemm<1, 1024><<<dim3(1024 / 128, NROWS / 128), thr, GM_SMEM>>>(
        hs, vw, nullptr, vrg, vsg, nullptr);
    // V prefix sums (centre-attention term)
    vseg_k<<<BATCH * HEADS * 8, 64>>>();
    vprefix_k<<<BATCH * HEADS * 8, 64>>>();
    // Tensor-core flash attention
    flash_mma<<<dim3(S_LEN / 128, BATCH * HEADS), thr, FL2_SMEM>>>(amr, ams, cag);
    // Output projection
    mma_gemm<2, 1024><<<dim3(1024 / 128, NROWS / 128), thr, GM_SMEM>>>(
        nullptr, pw, nullptr, prg, psg, out);
}

// round 9
// speedup vs baseline: 1.4282x; 1.0456x over previous
#include <cuda_runtime.h>
#include <cstdint>
#include <math.h>

#define S_LEN 2048
#define BATCH 2
#define EMB   1024
#define HEADS 16
#define HDIM  64
#define NROWS (BATCH*S_LEN)   // 4096

// Scratch (no allocations allowed)
__device__ float g_q[(size_t)BATCH*HEADS*S_LEN*HDIM];   // [bh][s][d], pre-scaled by 1/sqrt(D)
__device__ float g_k[(size_t)BATCH*HEADS*S_LEN*HDIM];
__device__ float g_v[(size_t)BATCH*HEADS*S_LEN*HDIM];
__device__ float g_vs[(size_t)BATCH*HEADS*S_LEN*HDIM];  // inclusive prefix sums of V over s
__device__ float g_ctx[(size_t)NROWS*EMB];              // [b*S+s][e]

// ---------------------------------------------------------------------------
// tf32 helpers (portable PTX, valid under compute_103 target)
// ---------------------------------------------------------------------------
__device__ __forceinline__ uint32_t f2tf32(float x) {
    uint32_t r;
    asm("cvt.rna.tf32.f32 %0, %1;" : "=r"(r) : "f"(x));
    return r;
}
__device__ __forceinline__ void split4(float4 v, uint4& h, uint4& l) {
    h.x = f2tf32(v.x); h.y = f2tf32(v.y); h.z = f2tf32(v.z); h.w = f2tf32(v.w);
    l.x = f2tf32(v.x - __uint_as_float(h.x));
    l.y = f2tf32(v.y - __uint_as_float(h.y));
    l.z = f2tf32(v.z - __uint_as_float(h.z));
    l.w = f2tf32(v.w - __uint_as_float(h.w));
}
// D += A*B, m16n8k8 tf32, row.col
__device__ __forceinline__ void mma8(float* d, const uint32_t* a, const uint32_t* b) {
    asm volatile(
        "mma.sync.aligned.m16n8k8.row.col.f32.tf32.tf32.f32 "
        "{%0,%1,%2,%3}, {%4,%5,%6,%7}, {%8,%9}, {%0,%1,%2,%3};"
        : "+f"(d[0]), "+f"(d[1]), "+f"(d[2]), "+f"(d[3])
        : "r"(a[0]), "r"(a[1]), "r"(a[2]), "r"(a[3]), "r"(b[0]), "r"(b[1]));
}

// Fast exp for x <= 0 on FMA/ALU pipes (avoids MUFU serialization).
__device__ __forceinline__ float fexp(float x) {
    float y = x * 1.4426950408889634f;
    y = fmaxf(y, -126.0f);
    float rn = y + 12582912.0f;                  // round-to-nearest magic
    int   n  = __float_as_int(rn) - 0x4B400000;
    float f  = y - (rn - 12582912.0f);
    float p = 1.3333558146e-3f;
    p = fmaf(p, f, 9.6181291076e-3f);
    p = fmaf(p, f, 5.5504108664e-2f);
    p = fmaf(p, f, 2.4022650695910072e-1f);
    p = fmaf(p, f, 6.9314718055994531e-1f);
    p = fmaf(p, f, 1.0f);
    return __int_as_float(__float_as_int(p) + (n << 23));
}

// ---------------------------------------------------------------------------
// tf32x3 tensor-core GEMM (unchanged, known-good): 128x128 CTA tile.
// ---------------------------------------------------------------------------
#define ASTRIDE 20
#define BSTRIDE 136
#define ABUF (128*ASTRIDE)
#define BBUF (16*BSTRIDE)
#define GM_SMEM ((2*ABUF*2 + 2*BBUF*2) * 4)

template<int MODE, int NDIM>
__global__ __launch_bounds__(256) void mma_gemm(
    const float* __restrict__ A, const float* __restrict__ W,
    const float* __restrict__ bias,
    const float* __restrict__ grp, const float* __restrict__ gsp,
    float* __restrict__ outp)
{
    constexpr int K = 1024;
    extern __shared__ float sm[];
    float* AsH = sm;
    float* AsL = AsH + 2 * ABUF;
    float* BsH = AsL + 2 * ABUF;
    float* BsL = BsH + 2 * BBUF;

    const float* Ap = (MODE == 2) ? g_ctx : A;

    int tid = threadIdx.x;
    int wid = tid >> 5, lane = tid & 31;
    int wr = wid >> 2, wc = wid & 3;
    int gid = lane >> 2, tig = lane & 3;
    int row0 = blockIdx.y * 128, col0 = blockIdx.x * 128;

    float acc[4][4][4];
    #pragma unroll
    for (int mt = 0; mt < 4; mt++)
        #pragma unroll
        for (int nt = 0; nt < 4; nt++)
            #pragma unroll
            for (int f = 0; f < 4; f++) acc[mt][nt][f] = 0.f;

    float4 pa[2], pb[2];

    auto ldg = [&](int kc) {
        int k0 = kc * 16;
        #pragma unroll
        for (int i = 0; i < 2; i++) {
            int idx = tid + i * 256;
            pa[i] = *(const float4*)(Ap + (size_t)(row0 + (idx >> 2)) * K + k0 + ((idx & 3) << 2));
            pb[i] = *(const float4*)(W + (size_t)(k0 + (idx >> 5)) * NDIM + col0 + ((idx & 31) << 2));
        }
    };
    auto sts = [&](int buf) {
        #pragma unroll
        for (int i = 0; i < 2; i++) {
            int idx = tid + i * 256;
            {
                int r = idx >> 2, kq = (idx & 3) << 2;
                uint4 h, l; split4(pa[i], h, l);
                *(uint4*)&AsH[buf * ABUF + r * ASTRIDE + kq] = h;
                *(uint4*)&AsL[buf * ABUF + r * ASTRIDE + kq] = l;
            }
            {
                int k = idx >> 5, n = (idx & 31) << 2;
                uint4 h, l; split4(pb[i], h, l);
                *(uint4*)&BsH[buf * BBUF + k * BSTRIDE + n] = h;
                *(uint4*)&BsL[buf * BBUF + k * BSTRIDE + n] = l;
            }
        }
    };

    ldg(0); sts(0);
    __syncthreads();

    for (int kc = 0; kc < 64; kc++) {
        int cb = kc & 1;
        if (kc < 63) ldg(kc + 1);

        #pragma unroll
        for (int k8 = 0; k8 < 2; k8++) {
            int kk = k8 * 8;
            uint32_t ah[4][4], al[4][4], bh[4][2], bl[4][2];
            #pragma unroll
            for (int mt = 0; mt < 4; mt++) {
                int r = wr * 64 + mt * 16 + gid;
                int base = cb * ABUF + r * ASTRIDE + kk + tig;
                ah[mt][0] = __float_as_uint(AsH[base]);
                ah[mt][1] = __float_as_uint(AsH[base + 8 * ASTRIDE]);
                ah[mt][2] = __float_as_uint(AsH[base + 4]);
                ah[mt][3] = __float_as_uint(AsH[base + 8 * ASTRIDE + 4]);
                al[mt][0] = __float_as_uint(AsL[base]);
                al[mt][1] = __float_as_uint(AsL[base + 8 * ASTRIDE]);
                al[mt][2] = __float_as_uint(AsL[base + 4]);
                al[mt][3] = __float_as_uint(AsL[base + 8 * ASTRIDE + 4]);
            }
            #pragma unroll
            for (int nt = 0; nt < 4; nt++) {
                int n = wc * 32 + nt * 8 + gid;
                int base = cb * BBUF + (kk + tig) * BSTRIDE + n;
                bh[nt][0] = __float_as_uint(BsH[base]);
                bh[nt][1] = __float_as_uint(BsH[base + 4 * BSTRIDE]);
                bl[nt][0] = __float_as_uint(BsL[base]);
                bl[nt][1] = __float_as_uint(BsL[base + 4 * BSTRIDE]);
            }
            #pragma unroll
            for (int mt = 0; mt < 4; mt++)
                #pragma unroll
                for (int nt = 0; nt < 4; nt++) {
                    mma8(acc[mt][nt], ah[mt], bh[nt]);
                    mma8(acc[mt][nt], al[mt], bh[nt]);
                    mma8(acc[mt][nt], ah[mt], bl[nt]);
                }
        }

        if (kc < 63) {
            sts((kc + 1) & 1);
            __syncthreads();
        }
    }

    float gr = 0.f, gs = 0.f;
    if (MODE == 1 || MODE == 2) { gr = *grp; gs = *gsp; }

    #pragma unroll
    for (int mt = 0; mt < 4; mt++) {
        #pragma unroll
        for (int nt = 0; nt < 4; nt++) {
            int rb = row0 + wr * 64 + mt * 16;
            int cb2 = col0 + wc * 32 + nt * 8;
            #pragma unroll
            for (int half = 0; half < 2; half++) {
                int r = rb + gid + half * 8;
                int b = r >> 11, s = r & (S_LEN - 1);
                #pragma unroll
                for (int e = 0; e < 2; e++) {
                    int c = cb2 + tig * 2 + e;
                    float v = acc[mt][nt][half * 2 + e];
                    if (MODE == 0) {
                        v += bias[c];
                        if (c < EMB) {
                            int h = c >> 6, d = c & 63;
                            g_q[(((size_t)(b * HEADS + h)) * S_LEN + s) * HDIM + d] = v * 0.125f;
                        } else {
                            int c2 = c - EMB;
                            int h = c2 >> 6, d = c2 & 63;
                            g_k[(((size_t)(b * HEADS + h)) * S_LEN + s) * HDIM + d] = v;
                        }
                    } else if (MODE == 1) {
                        int h = c >> 6, d = c & 63;
                        g_v[(((size_t)(b * HEADS + h)) * S_LEN + s) * HDIM + d] =
                            gr * v + gs * A[(size_t)r * K + c];
                    } else {
                        outp[(size_t)r * NDIM + c] =
                            gr * v + gs * g_ctx[(size_t)r * K + c];
                    }
                }
            }
        }
    }
}

// ---------------------------------------------------------------------------
// Fused V prefix-sum: g_vs[bh][s][d] = sum_{k<=s} g_v[bh][k][d].
// One CTA per bh; 512 threads = 32 s-chunks (64 rows) x 16 float4 d-groups.
// Phase 1: per-chunk partial sums -> smem. Phase 2: prefix base + stream.
// ---------------------------------------------------------------------------
__global__ __launch_bounds__(512) void vprefix2_k() {
    __shared__ float4 part[32][16];
    int bh = blockIdx.x;
    int ci = threadIdx.x >> 4;        // 0..31: chunk of 64 s-rows
    int dg = threadIdx.x & 15;        // float4 group in d

    const float4* vp = (const float4*)(g_v + ((size_t)bh * S_LEN + ci * 64) * 64) + dg;
    float4 acc = make_float4(0.f, 0.f, 0.f, 0.f);
    #pragma unroll 8
    for (int s = 0; s < 64; s++) {
        float4 t = vp[(size_t)s * 16];
        acc.x += t.x; acc.y += t.y; acc.z += t.z; acc.w += t.w;
    }
    part[ci][dg] = acc;
    __syncthreads();

    float4 base = make_float4(0.f, 0.f, 0.f, 0.f);
    for (int t = 0; t < ci; t++) {
        float4 p = part[t][dg];
        base.x += p.x; base.y += p.y; base.z += p.z; base.w += p.w;
    }

    float4* op = (float4*)(g_vs + ((size_t)bh * S_LEN + ci * 64) * 64) + dg;
    acc = base;
    #pragma unroll 8
    for (int s = 0; s < 64; s++) {
        float4 t = vp[(size_t)s * 16];
        acc.x += t.x; acc.y += t.y; acc.z += t.z; acc.w += t.w;
        op[(size_t)s * 16] = acc;
    }
}

// ---------------------------------------------------------------------------
// Tensor-core flash attention (tf32x3, unchanged, known-good)
// ---------------------------------------------------------------------------
#define KTSTR 136
#define KTBUF (64*KTSTR)
#define FL2_SMEM ((2*KTBUF + 2*KTBUF + 128*KTSTR) * 4)
#define NEG_BIG (-1.0e30f)

__global__ __launch_bounds__(256) void flash_mma(
    const float* __restrict__ gr_, const float* __restrict__ gs_,
    const float* __restrict__ gc_)
{
    extern __shared__ float smf[];
    float* KTb = smf;                    // [2][64 d][KTSTR]  (K transposed)
    float* VTb = smf + 2 * KTBUF;        // [2][64 k][KTSTR]  (V natural)
    float* PT  = smf + 4 * KTBUF;        // [128 q][KTSTR]

    int tid = threadIdx.x, wid = tid >> 5, lane = tid & 31;
    int gid = lane >> 2, tig = lane & 3;
    int qt = 15 - (int)blockIdx.x;       // big workloads first
    int bh = blockIdx.y;
    int qbase = qt * 128;
    int rAp = wid * 8 + gid, rBp = 64 + wid * 8 + gid;
    int qA = qbase + rAp, qB = qbase + rBp;

    uint32_t qh[8][4], ql[8][4];
    {
        const float* Qp = g_q + (size_t)bh * S_LEN * 64;
        #pragma unroll
        for (int k8 = 0; k8 < 8; k8++) {
            float v[4];
            v[0] = Qp[(size_t)qA * 64 + k8 * 8 + tig];
            v[1] = Qp[(size_t)qB * 64 + k8 * 8 + tig];
            v[2] = Qp[(size_t)qA * 64 + k8 * 8 + tig + 4];
            v[3] = Qp[(size_t)qB * 64 + k8 * 8 + tig + 4];
            #pragma unroll
            for (int j = 0; j < 4; j++) {
                qh[k8][j] = f2tf32(v[j]);
                ql[k8][j] = f2tf32(v[j] - __uint_as_float(qh[k8][j]));
            }
        }
    }

    float O[8][4];
    #pragma unroll
    for (int nf = 0; nf < 8; nf++)
        #pragma unroll
        for (int f = 0; f < 4; f++) O[nf][f] = 0.f;
    float mA = NEG_BIG, mB = NEG_BIG, lA = 0.f, lB = 0.f;

    const int kmax = 2 * qt + 2;

    float  kst[16];
    float4 vst[4];
    auto ldgKV = [&](int kt) {
        const float* Kg = g_k + ((size_t)bh * S_LEN + kt * 64) * 64;
        const float* Vg = g_v + ((size_t)bh * S_LEN + kt * 64) * 64;
        #pragma unroll
        for (int i = 0; i < 4; i++) {
            int idx = tid + i * 256;
            int d = idx & 63, kp4 = (idx >> 6) << 2;
            #pragma unroll
            for (int j = 0; j < 4; j++)
                kst[i * 4 + j] = Kg[(size_t)(kp4 + j) * 64 + d];
            int vk = idx >> 4, d4 = (idx & 15) << 2;
            vst[i] = *(const float4*)(Vg + (size_t)vk * 64 + d4);
        }
    };
    auto stsKV = [&](int buf) {
        float* kb0 = KTb + buf * KTBUF;
        float* vb0 = VTb + buf * KTBUF;
        #pragma unroll
        for (int i = 0; i < 4; i++) {
            int idx = tid + i * 256;
            int d = idx & 63, kp4 = (idx >> 6) << 2;
            float4 kv = make_float4(kst[i*4], kst[i*4+1], kst[i*4+2], kst[i*4+3]);
            uint4 kh, kl; split4(kv, kh, kl);
            float* kp = kb0 + d * KTSTR + kp4 * 2;
            *(float4*)kp = make_float4(__uint_as_float(kh.x), __uint_as_float(kl.x),
                                       __uint_as_float(kh.y), __uint_as_float(kl.y));
            *(float4*)(kp + 4) = make_float4(__uint_as_float(kh.z), __uint_as_float(kl.z),
                                             __uint_as_float(kh.w), __uint_as_float(kl.w));
            int vk = idx >> 4, d4 = (idx & 15) << 2;
            uint4 vh, vl; split4(vst[i], vh, vl);
            float* vp = vb0 + vk * KTSTR + d4 * 2;
            *(float4*)vp = make_float4(__uint_as_float(vh.x), __uint_as_float(vl.x),
                                       __uint_as_float(vh.y), __uint_as_float(vl.y));
            *(float4*)(vp + 4) = make_float4(__uint_as_float(vh.z), __uint_as_float(vl.z),
                                             __uint_as_float(vh.w), __uint_as_float(vl.w));
        }
    };

    ldgKV(0); stsKV(0);
    __syncthreads();

    for (int kt = 0; kt < kmax; kt++) {
        int buf = kt & 1;

        float sacc[8][4];
        #pragma unroll
        for (int nf = 0; nf < 8; nf++)
            #pragma unroll
            for (int f = 0; f < 4; f++) sacc[nf][f] = 0.f;
        {
            const float* kb = KTb + buf * KTBUF;
            #pragma unroll
            for (int k8 = 0; k8 < 8; k8++) {
                #pragma unroll
                for (int nf = 0; nf < 8; nf++) {
                    float2 b0 = *(const float2*)(kb + (k8*8 + tig) * KTSTR + (nf*8 + gid) * 2);
                    float2 b1 = *(const float2*)(kb + (k8*8 + tig + 4) * KTSTR + (nf*8 + gid) * 2);
                    uint32_t bhv[2] = {__float_as_uint(b0.x), __float_as_uint(b1.x)};
                    uint32_t blv[2] = {__float_as_uint(b0.y), __float_as_uint(b1.y)};
                    mma8(sacc[nf], qh[k8], bhv);
                    mma8(sacc[nf], ql[k8], bhv);
                    mma8(sacc[nf], qh[k8], blv);
                }
            }
        }

        if (kt + 1 < kmax) ldgKV(kt + 1);

        if (kt >= 2 * qt) {
            int c0g = kt * 64;
            #pragma unroll
            for (int nf = 0; nf < 8; nf++)
                #pragma unroll
                for (int e = 0; e < 2; e++) {
                    int col = c0g + nf * 8 + tig * 2 + e;
                    if (col > qA) sacc[nf][e]     = NEG_BIG;
                    if (col > qB) sacc[nf][2 + e] = NEG_BIG;
                }
        }

        float mxA = NEG_BIG, mxB = NEG_BIG;
        #pragma unroll
        for (int nf = 0; nf < 8; nf++) {
            mxA = fmaxf(mxA, fmaxf(sacc[nf][0], sacc[nf][1]));
            mxB = fmaxf(mxB, fmaxf(sacc[nf][2], sacc[nf][3]));
        }
        mxA = fmaxf(mxA, __shfl_xor_sync(0xffffffffu, mxA, 1));
        mxA = fmaxf(mxA, __shfl_xor_sync(0xffffffffu, mxA, 2));
        mxB = fmaxf(mxB, __shfl_xor_sync(0xffffffffu, mxB, 1));
        mxB = fmaxf(mxB, __shfl_xor_sync(0xffffffffu, mxB, 2));
        float mnA = fmaxf(mA, mxA), mnB = fmaxf(mB, mxB);
        float scA = fexp(mA - mnA), scB = fexp(mB - mnB);
        mA = mnA; mB = mnB;
        float sumA = 0.f, sumB = 0.f;
        #pragma unroll
        for (int nf = 0; nf < 8; nf++) {
            float p0 = fexp(sacc[nf][0] - mnA);
            float p1 = fexp(sacc[nf][1] - mnA);
            float p2 = fexp(sacc[nf][2] - mnB);
            float p3 = fexp(sacc[nf][3] - mnB);
            sumA += p0 + p1; sumB += p2 + p3;
            uint32_t h0 = f2tf32(p0), h1 = f2tf32(p1), h2 = f2tf32(p2), h3 = f2tf32(p3);
            uint32_t l0 = f2tf32(p0 - __uint_as_float(h0));
            uint32_t l1 = f2tf32(p1 - __uint_as_float(h1));
            uint32_t l2 = f2tf32(p2 - __uint_as_float(h2));
            uint32_t l3 = f2tf32(p3 - __uint_as_float(h3));
            int colo = (nf * 8 + tig * 2) * 2;
            *(float4*)(PT + rAp * KTSTR + colo) =
                make_float4(__uint_as_float(h0), __uint_as_float(l0),
                            __uint_as_float(h1), __uint_as_float(l1));
            *(float4*)(PT + rBp * KTSTR + colo) =
                make_float4(__uint_as_float(h2), __uint_as_float(l2),
                            __uint_as_float(h3), __uint_as_float(l3));
        }
        sumA += __shfl_xor_sync(0xffffffffu, sumA, 1);
        sumA += __shfl_xor_sync(0xffffffffu, sumA, 2);
        sumB += __shfl_xor_sync(0xffffffffu, sumB, 1);
        sumB += __shfl_xor_sync(0xffffffffu, sumB, 2);
        lA = lA * scA + sumA;
        lB = lB * scB + sumB;
        #pragma unroll
        for (int nf = 0; nf < 8; nf++) {
            O[nf][0] *= scA; O[nf][1] *= scA;
            O[nf][2] *= scB; O[nf][3] *= scB;
        }
        __syncwarp();

        if (kt + 1 < kmax) stsKV((kt + 1) & 1);

        {
            const float* vb = VTb + buf * KTBUF;
            #pragma unroll
            for (int k8 = 0; k8 < 8; k8++) {
                float2 a0 = *(const float2*)(PT + rAp * KTSTR + (k8*8 + tig) * 2);
                float2 a1 = *(const float2*)(PT + rBp * KTSTR + (k8*8 + tig) * 2);
                float2 a2 = *(const float2*)(PT + rAp * KTSTR + (k8*8 + tig + 4) * 2);
                float2 a3 = *(const float2*)(PT + rBp * KTSTR + (k8*8 + tig + 4) * 2);
                uint32_t ah[4] = {__float_as_uint(a0.x), __float_as_uint(a1.x),
                                  __float_as_uint(a2.x), __float_as_uint(a3.x)};
                uint32_t al[4] = {__float_as_uint(a0.y), __float_as_uint(a1.y),
                                  __float_as_uint(a2.y), __float_as_uint(a3.y)};
                #pragma unroll
                for (int nf = 0; nf < 8; nf++) {
                    float2 b0 = *(const float2*)(vb + (k8*8 + tig) * KTSTR + (nf*8 + gid) * 2);
                    float2 b1 = *(const float2*)(vb + (k8*8 + tig + 4) * KTSTR + (nf*8 + gid) * 2);
                    uint32_t bhv[2] = {__float_as_uint(b0.x), __float_as_uint(b1.x)};
                    uint32_t blv[2] = {__float_as_uint(b0.y), __float_as_uint(b1.y)};
                    mma8(O[nf], ah, bhv);
                    mma8(O[nf], al, bhv);
                    mma8(O[nf], ah, blv);
                }
            }
        }
        __syncthreads();
    }

    int h = bh & (HEADS - 1), b = bh >> 4;
    float grh = gr_[h], gsh = gs_[h], gch = gc_[h];
    float giA = grh / lA, giB = grh / lB;
    float cgA = gch / (float)(qA + 1), cgB = gch / (float)(qB + 1);
    const float* vrA  = g_v  + ((size_t)bh * S_LEN + qA) * 64;
    const float* vrB  = g_v  + ((size_t)bh * S_LEN + qB) * 64;
    const float* vsA  = g_vs + ((size_t)bh * S_LEN + qA) * 64;
    const float* vsB  = g_vs + ((size_t)bh * S_LEN + qB) * 64;
    float* oA = g_ctx + ((size_t)(b * S_LEN + qA)) * EMB + h * 64;
    float* oB = g_ctx + ((size_t)(b * S_LEN + qB)) * EMB + h * 64;
    #pragma unroll
    for (int nf = 0; nf < 8; nf++) {
        int d0 = nf * 8 + tig * 2;
        float2 vqA = *(const float2*)(vrA + d0);
        float2 vqB = *(const float2*)(vrB + d0);
        float2 psA = *(const float2*)(vsA + d0);
        float2 psB = *(const float2*)(vsB + d0);
        float2 ra, rb;
        ra.x = O[nf][0] * giA + gsh * vqA.x - cgA * psA.x;
        ra.y = O[nf][1] * giA + gsh * vqA.y - cgA * psA.y;
        rb.x = O[nf][2] * giB + gsh * vqB.x - cgB * psB.x;
        rb.y = O[nf][3] * giB + gsh * vqB.y - cgB * psB.y;
        *(float2*)(oA + d0) = ra;
        *(float2*)(oB + d0) = rb;
    }
}

// ---------------------------------------------------------------------------
extern "C" void kernel_launch(void* const* d_in, const int* in_sizes, int n_in,
                              void* d_out, int out_size)
{
    const float* hs   = (const float*)d_in[0];
    const float* qkw  = (const float*)d_in[1];
    const float* qkb  = (const float*)d_in[2];
    const float* vw   = (const float*)d_in[3];
    const float* vrg  = (const float*)d_in[4];
    const float* vsg  = (const float*)d_in[5];
    const float* pw   = (const float*)d_in[6];
    const float* prg  = (const float*)d_in[7];
    const float* psg  = (const float*)d_in[8];
    const float* amr  = (const float*)d_in[9];
    const float* ams  = (const float*)d_in[10];
    const float* cag  = (const float*)d_in[11];
    float* out = (float*)d_out;

    // Host-side resources created once (host state only; launched work is
    // identical on every call).
    static cudaStream_t s2 = nullptr;
    static cudaEvent_t evV = nullptr, evP = nullptr;
    if (s2 == nullptr) {
        cudaStreamCreateWithFlags(&s2, cudaStreamNonBlocking);
        cudaEventCreateWithFlags(&evV, cudaEventDisableTiming);
        cudaEventCreateWithFlags(&evP, cudaEventDisableTiming);
    }

    cudaFuncSetAttribute(mma_gemm<0, 2048>, cudaFuncAttributeMaxDynamicSharedMemorySize, GM_SMEM);
    cudaFuncSetAttribute(mma_gemm<1, 1024>, cudaFuncAttributeMaxDynamicSharedMemorySize, GM_SMEM);
    cudaFuncSetAttribute(mma_gemm<2, 1024>, cudaFuncAttributeMaxDynamicSharedMemorySize, GM_SMEM);
    cudaFuncSetAttribute(flash_mma, cudaFuncAttributeMaxDynamicSharedMemorySize, FL2_SMEM);

    dim3 thr(256);
    // V projection first (producer of g_v)
    mma_gemm<1, 1024><<<dim3(1024 / 128, NROWS / 128), thr, GM_SMEM>>>(
        hs, vw, nullptr, vrg, vsg, nullptr);
    // Fork: V prefix-sum on side stream, overlapped with QK projection
    cudaEventRecord(evV, 0);
    cudaStreamWaitEvent(s2, evV, 0);
    vprefix2_k<<<BATCH * HEADS, 512, 0, s2>>>();
    // QK projection (independent of g_v) on main stream
    mma_gemm<0, 2048><<<dim3(2048 / 128, NROWS / 128), thr, GM_SMEM>>>(
        hs, qkw, qkb, nullptr, nullptr, nullptr);
    // Join
    cudaEventRecord(evP, s2);
    cudaStreamWaitEvent(0, evP, 0);
    // Tensor-core flash attention
    flash_mma<<<dim3(S_LEN / 128, BATCH * HEADS), thr, FL2_SMEM>>>(amr, ams, cag);
    // Output projection
    mma_gemm<2, 1024><<<dim3(1024 / 128, NROWS / 128), thr, GM_SMEM>>>(
        nullptr, pw, nullptr, prg, psg, out);
}

// round 10
// speedup vs baseline: 1.5906x; 1.1137x over previous
#include <cuda_runtime.h>
#include <cstdint>
#include <math.h>

#define S_LEN 2048
#define BATCH 2
#define EMB   1024
#define HEADS 16
#define HDIM  64
#define NROWS (BATCH*S_LEN)   // 4096

// Scratch (no allocations allowed)
__device__ float g_q[(size_t)BATCH*HEADS*S_LEN*HDIM];   // [bh][s][d], pre-scaled by 1/sqrt(D)
__device__ float g_k[(size_t)BATCH*HEADS*S_LEN*HDIM];
__device__ float g_v[(size_t)BATCH*HEADS*S_LEN*HDIM];
__device__ float g_vs[(size_t)BATCH*HEADS*S_LEN*HDIM];  // inclusive prefix sums of V over s
__device__ float g_ctx[(size_t)NROWS*EMB];              // [b*S+s][e]

// ---------------------------------------------------------------------------
// tf32 helpers (portable PTX, valid under compute_103 target)
// ---------------------------------------------------------------------------
__device__ __forceinline__ uint32_t f2tf32(float x) {
    uint32_t r;
    asm("cvt.rna.tf32.f32 %0, %1;" : "=r"(r) : "f"(x));
    return r;
}
__device__ __forceinline__ void split4(float4 v, uint4& h, uint4& l) {
    h.x = f2tf32(v.x); h.y = f2tf32(v.y); h.z = f2tf32(v.z); h.w = f2tf32(v.w);
    l.x = f2tf32(v.x - __uint_as_float(h.x));
    l.y = f2tf32(v.y - __uint_as_float(h.y));
    l.z = f2tf32(v.z - __uint_as_float(h.z));
    l.w = f2tf32(v.w - __uint_as_float(h.w));
}
// D += A*B, m16n8k8 tf32, row.col
__device__ __forceinline__ void mma8(float* d, const uint32_t* a, const uint32_t* b) {
    asm volatile(
        "mma.sync.aligned.m16n8k8.row.col.f32.tf32.tf32.f32 "
        "{%0,%1,%2,%3}, {%4,%5,%6,%7}, {%8,%9}, {%0,%1,%2,%3};"
        : "+f"(d[0]), "+f"(d[1]), "+f"(d[2]), "+f"(d[3])
        : "r"(a[0]), "r"(a[1]), "r"(a[2]), "r"(a[3]), "r"(b[0]), "r"(b[1]));
}

// Fast exp for x <= 0 on FMA/ALU pipes (avoids MUFU serialization).
__device__ __forceinline__ float fexp(float x) {
    float y = x * 1.4426950408889634f;
    y = fmaxf(y, -126.0f);
    float rn = y + 12582912.0f;                  // round-to-nearest magic
    int   n  = __float_as_int(rn) - 0x4B400000;
    float f  = y - (rn - 12582912.0f);
    float p = 1.3333558146e-3f;
    p = fmaf(p, f, 9.6181291076e-3f);
    p = fmaf(p, f, 5.5504108664e-2f);
    p = fmaf(p, f, 2.4022650695910072e-1f);
    p = fmaf(p, f, 6.9314718055994531e-1f);
    p = fmaf(p, f, 1.0f);
    return __int_as_float(__float_as_int(p) + (n << 23));
}

// ---------------------------------------------------------------------------
// tf32x3 tensor-core GEMM, raw-fp32 smem tiles, hi/lo split in registers.
// 128x128 CTA tile, 8 warps (2x4), BK=16 double-buffered.
// ---------------------------------------------------------------------------
#define ASTRIDE 20
#define BSTRIDE 136
#define ABUF (128*ASTRIDE)   // raw A tile floats
#define BBUF (16*BSTRIDE)    // raw B tile floats
#define GM_SMEM ((2*ABUF + 2*BBUF) * 4)   // 37888 bytes

template<int MODE, int NDIM>
__global__ __launch_bounds__(256) void mma_gemm(
    const float* __restrict__ A, const float* __restrict__ W,
    const float* __restrict__ bias,
    const float* __restrict__ grp, const float* __restrict__ gsp,
    float* __restrict__ outp)
{
    constexpr int K = 1024;
    extern __shared__ float sm[];
    float* As = sm;                 // [2][128][ASTRIDE] raw fp32
    float* Bs = As + 2 * ABUF;      // [2][16][BSTRIDE]  raw fp32

    const float* Ap = (MODE == 2) ? g_ctx : A;

    int tid = threadIdx.x;
    int wid = tid >> 5, lane = tid & 31;
    int wr = wid >> 2, wc = wid & 3;
    int gid = lane >> 2, tig = lane & 3;
    int row0 = blockIdx.y * 128, col0 = blockIdx.x * 128;

    float acc[4][4][4];
    #pragma unroll
    for (int mt = 0; mt < 4; mt++)
        #pragma unroll
        for (int nt = 0; nt < 4; nt++)
            #pragma unroll
            for (int f = 0; f < 4; f++) acc[mt][nt][f] = 0.f;

    float4 pa[2], pb[2];

    auto ldg = [&](int kc) {
        int k0 = kc * 16;
        #pragma unroll
        for (int i = 0; i < 2; i++) {
            int idx = tid + i * 256;
            pa[i] = *(const float4*)(Ap + (size_t)(row0 + (idx >> 2)) * K + k0 + ((idx & 3) << 2));
            pb[i] = *(const float4*)(W + (size_t)(k0 + (idx >> 5)) * NDIM + col0 + ((idx & 31) << 2));
        }
    };
    auto sts = [&](int buf) {
        #pragma unroll
        for (int i = 0; i < 2; i++) {
            int idx = tid + i * 256;
            *(float4*)&As[buf * ABUF + (idx >> 2) * ASTRIDE + ((idx & 3) << 2)] = pa[i];
            *(float4*)&Bs[buf * BBUF + (idx >> 5) * BSTRIDE + ((idx & 31) << 2)] = pb[i];
        }
    };

    ldg(0); sts(0);
    __syncthreads();

    for (int kc = 0; kc < 64; kc++) {
        int cb = kc & 1;
        if (kc < 63) ldg(kc + 1);

        #pragma unroll
        for (int k8 = 0; k8 < 2; k8++) {
            int kk = k8 * 8;
            uint32_t ah[4][4], al[4][4], bh[4][2], bl[4][2];
            #pragma unroll
            for (int mt = 0; mt < 4; mt++) {
                int r = wr * 64 + mt * 16 + gid;
                int base = cb * ABUF + r * ASTRIDE + kk + tig;
                float r0 = As[base];
                float r1 = As[base + 8 * ASTRIDE];
                float r2 = As[base + 4];
                float r3 = As[base + 8 * ASTRIDE + 4];
                ah[mt][0] = f2tf32(r0); al[mt][0] = f2tf32(r0 - __uint_as_float(ah[mt][0]));
                ah[mt][1] = f2tf32(r1); al[mt][1] = f2tf32(r1 - __uint_as_float(ah[mt][1]));
                ah[mt][2] = f2tf32(r2); al[mt][2] = f2tf32(r2 - __uint_as_float(ah[mt][2]));
                ah[mt][3] = f2tf32(r3); al[mt][3] = f2tf32(r3 - __uint_as_float(ah[mt][3]));
            }
            #pragma unroll
            for (int nt = 0; nt < 4; nt++) {
                int n = wc * 32 + nt * 8 + gid;
                int base = cb * BBUF + (kk + tig) * BSTRIDE + n;
                float r0 = Bs[base];
                float r1 = Bs[base + 4 * BSTRIDE];
                bh[nt][0] = f2tf32(r0); bl[nt][0] = f2tf32(r0 - __uint_as_float(bh[nt][0]));
                bh[nt][1] = f2tf32(r1); bl[nt][1] = f2tf32(r1 - __uint_as_float(bh[nt][1]));
            }
            #pragma unroll
            for (int mt = 0; mt < 4; mt++)
                #pragma unroll
                for (int nt = 0; nt < 4; nt++) {
                    mma8(acc[mt][nt], ah[mt], bh[nt]);
                    mma8(acc[mt][nt], al[mt], bh[nt]);
                    mma8(acc[mt][nt], ah[mt], bl[nt]);
                }
        }

        if (kc < 63) {
            sts((kc + 1) & 1);
            __syncthreads();
        }
    }

    float gr = 0.f, gs = 0.f;
    if (MODE == 1 || MODE == 2) { gr = *grp; gs = *gsp; }

    #pragma unroll
    for (int mt = 0; mt < 4; mt++) {
        #pragma unroll
        for (int nt = 0; nt < 4; nt++) {
            int rb = row0 + wr * 64 + mt * 16;
            int cb2 = col0 + wc * 32 + nt * 8;
            #pragma unroll
            for (int half = 0; half < 2; half++) {
                int r = rb + gid + half * 8;
                int b = r >> 11, s = r & (S_LEN - 1);
                #pragma unroll
                for (int e = 0; e < 2; e++) {
                    int c = cb2 + tig * 2 + e;
                    float v = acc[mt][nt][half * 2 + e];
                    if (MODE == 0) {
                        v += bias[c];
                        if (c < EMB) {
                            int h = c >> 6, d = c & 63;
                            g_q[(((size_t)(b * HEADS + h)) * S_LEN + s) * HDIM + d] = v * 0.125f;
                        } else {
                            int c2 = c - EMB;
                            int h = c2 >> 6, d = c2 & 63;
                            g_k[(((size_t)(b * HEADS + h)) * S_LEN + s) * HDIM + d] = v;
                        }
                    } else if (MODE == 1) {
                        int h = c >> 6, d = c & 63;
                        g_v[(((size_t)(b * HEADS + h)) * S_LEN + s) * HDIM + d] =
                            gr * v + gs * A[(size_t)r * K + c];
                    } else {
                        outp[(size_t)r * NDIM + c] =
                            gr * v + gs * g_ctx[(size_t)r * K + c];
                    }
                }
            }
        }
    }
}

// ---------------------------------------------------------------------------
// Fused V prefix-sum (unchanged, overlapped with QK GEMM)
// ---------------------------------------------------------------------------
__global__ __launch_bounds__(512) void vprefix2_k() {
    __shared__ float4 part[32][16];
    int bh = blockIdx.x;
    int ci = threadIdx.x >> 4;
    int dg = threadIdx.x & 15;

    const float4* vp = (const float4*)(g_v + ((size_t)bh * S_LEN + ci * 64) * 64) + dg;
    float4 acc = make_float4(0.f, 0.f, 0.f, 0.f);
    #pragma unroll 8
    for (int s = 0; s < 64; s++) {
        float4 t = vp[(size_t)s * 16];
        acc.x += t.x; acc.y += t.y; acc.z += t.z; acc.w += t.w;
    }
    part[ci][dg] = acc;
    __syncthreads();

    float4 base = make_float4(0.f, 0.f, 0.f, 0.f);
    for (int t = 0; t < ci; t++) {
        float4 p = part[t][dg];
        base.x += p.x; base.y += p.y; base.z += p.z; base.w += p.w;
    }

    float4* op = (float4*)(g_vs + ((size_t)bh * S_LEN + ci * 64) * 64) + dg;
    acc = base;
    #pragma unroll 8
    for (int s = 0; s < 64; s++) {
        float4 t = vp[(size_t)s * 16];
        acc.x += t.x; acc.y += t.y; acc.z += t.z; acc.w += t.w;
        op[(size_t)s * 16] = acc;
    }
}

// ---------------------------------------------------------------------------
// Tensor-core flash attention: QK^T in tf32x3, P@V in single tf32.
// K smem keeps {hi,lo} pairs (stride 136); V and P are hi-only
// (strides 72 / 68, both conflict-free for their fragment patterns).
// ---------------------------------------------------------------------------
#define KTSTR 136
#define VSTR  72
#define PSTR  68
#define KTBUF (64*KTSTR)                 // 8704 floats per K buffer
#define VBUF  (64*VSTR)                  // 4608 floats per V buffer
#define FL2_SMEM ((2*KTBUF + 2*VBUF + 128*PSTR) * 4)   // 141312 B
#define NEG_BIG (-1.0e30f)

__global__ __launch_bounds__(256) void flash_mma(
    const float* __restrict__ gr_, const float* __restrict__ gs_,
    const float* __restrict__ gc_)
{
    extern __shared__ float smf[];
    float* KTb = smf;                    // [2][64 d][KTSTR]  K transposed {hi,lo}
    float* Vb  = smf + 2 * KTBUF;        // [2][64 k][VSTR]   V hi-only
    float* PT  = smf + 2 * KTBUF + 2 * VBUF;   // [128 q][PSTR]  P hi-only

    int tid = threadIdx.x, wid = tid >> 5, lane = tid & 31;
    int gid = lane >> 2, tig = lane & 3;
    int qt = 15 - (int)blockIdx.x;       // big workloads first
    int bh = blockIdx.y;
    int qbase = qt * 128;
    int rAp = wid * 8 + gid, rBp = 64 + wid * 8 + gid;
    int qA = qbase + rAp, qB = qbase + rBp;

    uint32_t qh[8][4], ql[8][4];
    {
        const float* Qp = g_q + (size_t)bh * S_LEN * 64;
        #pragma unroll
        for (int k8 = 0; k8 < 8; k8++) {
            float v[4];
            v[0] = Qp[(size_t)qA * 64 + k8 * 8 + tig];
            v[1] = Qp[(size_t)qB * 64 + k8 * 8 + tig];
            v[2] = Qp[(size_t)qA * 64 + k8 * 8 + tig + 4];
            v[3] = Qp[(size_t)qB * 64 + k8 * 8 + tig + 4];
            #pragma unroll
            for (int j = 0; j < 4; j++) {
                qh[k8][j] = f2tf32(v[j]);
                ql[k8][j] = f2tf32(v[j] - __uint_as_float(qh[k8][j]));
            }
        }
    }

    float O[8][4];
    #pragma unroll
    for (int nf = 0; nf < 8; nf++)
        #pragma unroll
        for (int f = 0; f < 4; f++) O[nf][f] = 0.f;
    float mA = NEG_BIG, mB = NEG_BIG, lA = 0.f, lB = 0.f;

    const int kmax = 2 * qt + 2;

    float  kst[16];
    float4 vst[4];
    auto ldgKV = [&](int kt) {
        const float* Kg = g_k + ((size_t)bh * S_LEN + kt * 64) * 64;
        const float* Vg = g_v + ((size_t)bh * S_LEN + kt * 64) * 64;
        #pragma unroll
        for (int i = 0; i < 4; i++) {
            int idx = tid + i * 256;
            int d = idx & 63, kp4 = (idx >> 6) << 2;
            #pragma unroll
            for (int j = 0; j < 4; j++)
                kst[i * 4 + j] = Kg[(size_t)(kp4 + j) * 64 + d];
            int vk = idx >> 4, d4 = (idx & 15) << 2;
            vst[i] = *(const float4*)(Vg + (size_t)vk * 64 + d4);
        }
    };
    auto stsKV = [&](int buf) {
        float* kb0 = KTb + buf * KTBUF;
        float* vb0 = Vb + buf * VBUF;
        #pragma unroll
        for (int i = 0; i < 4; i++) {
            int idx = tid + i * 256;
            int d = idx & 63, kp4 = (idx >> 6) << 2;
            float4 kv = make_float4(kst[i*4], kst[i*4+1], kst[i*4+2], kst[i*4+3]);
            uint4 kh, kl; split4(kv, kh, kl);
            float* kp = kb0 + d * KTSTR + kp4 * 2;
            *(float4*)kp = make_float4(__uint_as_float(kh.x), __uint_as_float(kl.x),
                                       __uint_as_float(kh.y), __uint_as_float(kl.y));
            *(float4*)(kp + 4) = make_float4(__uint_as_float(kh.z), __uint_as_float(kl.z),
                                             __uint_as_float(kh.w), __uint_as_float(kl.w));
            int vk = idx >> 4, d4 = (idx & 15) << 2;
            float4 vh4;
            vh4.x = __uint_as_float(f2tf32(vst[i].x));
            vh4.y = __uint_as_float(f2tf32(vst[i].y));
            vh4.z = __uint_as_float(f2tf32(vst[i].z));
            vh4.w = __uint_as_float(f2tf32(vst[i].w));
            *(float4*)(vb0 + vk * VSTR + d4) = vh4;
        }
    };

    ldgKV(0); stsKV(0);
    __syncthreads();

    for (int kt = 0; kt < kmax; kt++) {
        int buf = kt & 1;

        // S = Q @ K^T (tf32x3)
        float sacc[8][4];
        #pragma unroll
        for (int nf = 0; nf < 8; nf++)
            #pragma unroll
            for (int f = 0; f < 4; f++) sacc[nf][f] = 0.f;
        {
            const float* kb = KTb + buf * KTBUF;
            #pragma unroll
            for (int k8 = 0; k8 < 8; k8++) {
                #pragma unroll
                for (int nf = 0; nf < 8; nf++) {
                    float2 b0 = *(const float2*)(kb + (k8*8 + tig) * KTSTR + (nf*8 + gid) * 2);
                    float2 b1 = *(const float2*)(kb + (k8*8 + tig + 4) * KTSTR + (nf*8 + gid) * 2);
                    uint32_t bhv[2] = {__float_as_uint(b0.x), __float_as_uint(b1.x)};
                    uint32_t blv[2] = {__float_as_uint(b0.y), __float_as_uint(b1.y)};
                    mma8(sacc[nf], qh[k8], bhv);
                    mma8(sacc[nf], ql[k8], bhv);
                    mma8(sacc[nf], qh[k8], blv);
                }
            }
        }

        if (kt + 1 < kmax) ldgKV(kt + 1);

        if (kt >= 2 * qt) {
            int c0g = kt * 64;
            #pragma unroll
            for (int nf = 0; nf < 8; nf++)
                #pragma unroll
                for (int e = 0; e < 2; e++) {
                    int col = c0g + nf * 8 + tig * 2 + e;
                    if (col > qA) sacc[nf][e]     = NEG_BIG;
                    if (col > qB) sacc[nf][2 + e] = NEG_BIG;
                }
        }

        float mxA = NEG_BIG, mxB = NEG_BIG;
        #pragma unroll
        for (int nf = 0; nf < 8; nf++) {
            mxA = fmaxf(mxA, fmaxf(sacc[nf][0], sacc[nf][1]));
            mxB = fmaxf(mxB, fmaxf(sacc[nf][2], sacc[nf][3]));
        }
        mxA = fmaxf(mxA, __shfl_xor_sync(0xffffffffu, mxA, 1));
        mxA = fmaxf(mxA, __shfl_xor_sync(0xffffffffu, mxA, 2));
        mxB = fmaxf(mxB, __shfl_xor_sync(0xffffffffu, mxB, 1));
        mxB = fmaxf(mxB, __shfl_xor_sync(0xffffffffu, mxB, 2));
        float mnA = fmaxf(mA, mxA), mnB = fmaxf(mB, mxB);
        float scA = fexp(mA - mnA), scB = fexp(mB - mnB);
        mA = mnA; mB = mnB;
        float sumA = 0.f, sumB = 0.f;
        #pragma unroll
        for (int nf = 0; nf < 8; nf++) {
            float p0 = fexp(sacc[nf][0] - mnA);
            float p1 = fexp(sacc[nf][1] - mnA);
            float p2 = fexp(sacc[nf][2] - mnB);
            float p3 = fexp(sacc[nf][3] - mnB);
            sumA += p0 + p1; sumB += p2 + p3;
            int colo = nf * 8 + tig * 2;
            *(float2*)(PT + rAp * PSTR + colo) =
                make_float2(__uint_as_float(f2tf32(p0)), __uint_as_float(f2tf32(p1)));
            *(float2*)(PT + rBp * PSTR + colo) =
                make_float2(__uint_as_float(f2tf32(p2)), __uint_as_float(f2tf32(p3)));
        }
        sumA += __shfl_xor_sync(0xffffffffu, sumA, 1);
        sumA += __shfl_xor_sync(0xffffffffu, sumA, 2);
        sumB += __shfl_xor_sync(0xffffffffu, sumB, 1);
        sumB += __shfl_xor_sync(0xffffffffu, sumB, 2);
        lA = lA * scA + sumA;
        lB = lB * scB + sumB;
        #pragma unroll
        for (int nf = 0; nf < 8; nf++) {
            O[nf][0] *= scA; O[nf][1] *= scA;
            O[nf][2] *= scB; O[nf][3] *= scB;
        }
        __syncwarp();

        if (kt + 1 < kmax) stsKV((kt + 1) & 1);

        // O += P @ V  (single tf32: P hi, V hi)
        {
            const float* vb = Vb + buf * VBUF;
            #pragma unroll
            for (int k8 = 0; k8 < 8; k8++) {
                uint32_t ap[4];
                ap[0] = __float_as_uint(PT[rAp * PSTR + k8 * 8 + tig]);
                ap[1] = __float_as_uint(PT[rBp * PSTR + k8 * 8 + tig]);
                ap[2] = __float_as_uint(PT[rAp * PSTR + k8 * 8 + tig + 4]);
                ap[3] = __float_as_uint(PT[rBp * PSTR + k8 * 8 + tig + 4]);
                #pragma unroll
                for (int nf = 0; nf < 8; nf++) {
                    uint32_t bv[2];
                    bv[0] = __float_as_uint(vb[(k8*8 + tig) * VSTR + nf*8 + gid]);
                    bv[1] = __float_as_uint(vb[(k8*8 + tig + 4) * VSTR + nf*8 + gid]);
                    mma8(O[nf], ap, bv);
                }
            }
        }
        __syncthreads();
    }

    int h = bh & (HEADS - 1), b = bh >> 4;
    float grh = gr_[h], gsh = gs_[h], gch = gc_[h];
    float giA = grh / lA, giB = grh / lB;
    float cgA = gch / (float)(qA + 1), cgB = gch / (float)(qB + 1);
    const float* vrA  = g_v  + ((size_t)bh * S_LEN + qA) * 64;
    const float* vrB  = g_v  + ((size_t)bh * S_LEN + qB) * 64;
    const float* vsA  = g_vs + ((size_t)bh * S_LEN + qA) * 64;
    const float* vsB  = g_vs + ((size_t)bh * S_LEN + qB) * 64;
    float* oA = g_ctx + ((size_t)(b * S_LEN + qA)) * EMB + h * 64;
    float* oB = g_ctx + ((size_t)(b * S_LEN + qB)) * EMB + h * 64;
    #pragma unroll
    for (int nf = 0; nf < 8; nf++) {
        int d0 = nf * 8 + tig * 2;
        float2 vqA = *(const float2*)(vrA + d0);
        float2 vqB = *(const float2*)(vrB + d0);
        float2 psA = *(const float2*)(vsA + d0);
        float2 psB = *(const float2*)(vsB + d0);
        float2 ra, rb;
        ra.x = O[nf][0] * giA + gsh * vqA.x - cgA * psA.x;
        ra.y = O[nf][1] * giA + gsh * vqA.y - cgA * psA.y;
        rb.x = O[nf][2] * giB + gsh * vqB.x - cgB * psB.x;
        rb.y = O[nf][3] * giB + gsh * vqB.y - cgB * psB.y;
        *(float2*)(oA + d0) = ra;
        *(float2*)(oB + d0) = rb;
    }
}

// ---------------------------------------------------------------------------
extern "C" void kernel_launch(void* const* d_in, const int* in_sizes, int n_in,
                              void* d_out, int out_size)
{
    const float* hs   = (const float*)d_in[0];
    const float* qkw  = (const float*)d_in[1];
    const float* qkb  = (const float*)d_in[2];
    const float* vw   = (const float*)d_in[3];
    const float* vrg  = (const float*)d_in[4];
    const float* vsg  = (const float*)d_in[5];
    const float* pw   = (const float*)d_in[6];
    const float* prg  = (const float*)d_in[7];
    const float* psg  = (const float*)d_in[8];
    const float* amr  = (const float*)d_in[9];
    const float* ams  = (const float*)d_in[10];
    const float* cag  = (const float*)d_in[11];
    float* out = (float*)d_out;

    static cudaStream_t s2 = nullptr;
    static cudaEvent_t evV = nullptr, evP = nullptr;
    if (s2 == nullptr) {
        cudaStreamCreateWithFlags(&s2, cudaStreamNonBlocking);
        cudaEventCreateWithFlags(&evV, cudaEventDisableTiming);
        cudaEventCreateWithFlags(&evP, cudaEventDisableTiming);
    }

    cudaFuncSetAttribute(mma_gemm<0, 2048>, cudaFuncAttributeMaxDynamicSharedMemorySize, GM_SMEM);
    cudaFuncSetAttribute(mma_gemm<1, 1024>, cudaFuncAttributeMaxDynamicSharedMemorySize, GM_SMEM);
    cudaFuncSetAttribute(mma_gemm<2, 1024>, cudaFuncAttributeMaxDynamicSharedMemorySize, GM_SMEM);
    cudaFuncSetAttribute(flash_mma, cudaFuncAttributeMaxDynamicSharedMemorySize, FL2_SMEM);

    dim3 thr(256);
    // V projection first (producer of g_v)
    mma_gemm<1, 1024><<<dim3(1024 / 128, NROWS / 128), thr, GM_SMEM>>>(
        hs, vw, nullptr, vrg, vsg, nullptr);
    // Fork: V prefix-sum on side stream, overlapped with QK projection
    cudaEventRecord(evV, 0);
    cudaStreamWaitEvent(s2, evV, 0);
    vprefix2_k<<<BATCH * HEADS, 512, 0, s2>>>();
    // QK projection on main stream
    mma_gemm<0, 2048><<<dim3(2048 / 128, NROWS / 128), thr, GM_SMEM>>>(
        hs, qkw, qkb, nullptr, nullptr, nullptr);
    // Join
    cudaEventRecord(evP, s2);
    cudaStreamWaitEvent(0, evP, 0);
    // Tensor-core flash attention
    flash_mma<<<dim3(S_LEN / 128, BATCH * HEADS), thr, FL2_SMEM>>>(amr, ams, cag);
    // Output projection
    mma_gemm<2, 1024><<<dim3(1024 / 128, NROWS / 128), thr, GM_SMEM>>>(
        nullptr, pw, nullptr, prg, psg, out);
}

// round 11
// speedup vs baseline: 2.2230x; 1.3975x over previous
#include <cuda_runtime.h>
#include <cstdint>
#include <math.h>

#define S_LEN 2048
#define BATCH 2
#define EMB   1024
#define HEADS 16
#define HDIM  64
#define NROWS (BATCH*S_LEN)   // 4096

// Scratch (no allocations allowed)
__device__ float g_q[(size_t)BATCH*HEADS*S_LEN*HDIM];   // [bh][s][d], pre-scaled by 1/sqrt(D)
__device__ float g_k[(size_t)BATCH*HEADS*S_LEN*HDIM];
__device__ float g_v[(size_t)BATCH*HEADS*S_LEN*HDIM];
__device__ float g_vs[(size_t)BATCH*HEADS*S_LEN*HDIM];  // inclusive prefix sums of V over s
__device__ float g_ctx[(size_t)NROWS*EMB];              // [b*S+s][e]

// ---------------------------------------------------------------------------
// tf32 / bf16 helpers (portable PTX, valid under compute_103 target)
// ---------------------------------------------------------------------------
__device__ __forceinline__ uint32_t f2tf32(float x) {
    uint32_t r;
    asm("cvt.rna.tf32.f32 %0, %1;" : "=r"(r) : "f"(x));
    return r;
}
__device__ __forceinline__ void split4(float4 v, uint4& h, uint4& l) {
    h.x = f2tf32(v.x); h.y = f2tf32(v.y); h.z = f2tf32(v.z); h.w = f2tf32(v.w);
    l.x = f2tf32(v.x - __uint_as_float(h.x));
    l.y = f2tf32(v.y - __uint_as_float(h.y));
    l.z = f2tf32(v.z - __uint_as_float(h.z));
    l.w = f2tf32(v.w - __uint_as_float(h.w));
}
// D += A*B, m16n8k8 tf32, row.col
__device__ __forceinline__ void mma8(float* d, const uint32_t* a, const uint32_t* b) {
    asm volatile(
        "mma.sync.aligned.m16n8k8.row.col.f32.tf32.tf32.f32 "
        "{%0,%1,%2,%3}, {%4,%5,%6,%7}, {%8,%9}, {%0,%1,%2,%3};"
        : "+f"(d[0]), "+f"(d[1]), "+f"(d[2]), "+f"(d[3])
        : "r"(a[0]), "r"(a[1]), "r"(a[2]), "r"(a[3]), "r"(b[0]), "r"(b[1]));
}
// D += A*B, m16n8k16 bf16, row.col
__device__ __forceinline__ void mma16(float* d, const uint32_t* a, const uint32_t* b) {
    asm volatile(
        "mma.sync.aligned.m16n8k16.row.col.f32.bf16.bf16.f32 "
        "{%0,%1,%2,%3}, {%4,%5,%6,%7}, {%8,%9}, {%0,%1,%2,%3};"
        : "+f"(d[0]), "+f"(d[1]), "+f"(d[2]), "+f"(d[3])
        : "r"(a[0]), "r"(a[1]), "r"(a[2]), "r"(a[3]), "r"(b[0]), "r"(b[1]));
}
// pack two floats to bf16x2: result = {hi:bf16(yhi), lo:bf16(xlo)}
__device__ __forceinline__ uint32_t packbf(float yhi, float xlo) {
    uint32_t r;
    asm("cvt.rn.bf16x2.f32 %0, %1, %2;" : "=r"(r) : "f"(yhi), "f"(xlo));
    return r;
}
__device__ __forceinline__ float lowbf(uint32_t p)  { return __uint_as_float(p << 16); }
__device__ __forceinline__ float highbf(uint32_t p) { return __uint_as_float(p & 0xFFFF0000u); }
// split a (x, y) pair into hi/lo bf16x2 words
__device__ __forceinline__ void splitbf2(float x, float y, uint32_t& h, uint32_t& l) {
    h = packbf(y, x);
    l = packbf(y - highbf(h), x - lowbf(h));
}

// Fast exp for x <= 0 on FMA/ALU pipes (avoids MUFU serialization).
__device__ __forceinline__ float fexp(float x) {
    float y = x * 1.4426950408889634f;
    y = fmaxf(y, -126.0f);
    float rn = y + 12582912.0f;                  // round-to-nearest magic
    int   n  = __float_as_int(rn) - 0x4B400000;
    float f  = y - (rn - 12582912.0f);
    float p = 1.3333558146e-3f;
    p = fmaf(p, f, 9.6181291076e-3f);
    p = fmaf(p, f, 5.5504108664e-2f);
    p = fmaf(p, f, 2.4022650695910072e-1f);
    p = fmaf(p, f, 6.9314718055994531e-1f);
    p = fmaf(p, f, 1.0f);
    return __int_as_float(__float_as_int(p) + (n << 23));
}

// ---------------------------------------------------------------------------
// bf16x3 tensor-core GEMM (Markidis): C = Ah@Bh + Al@Bh + Ah@Bl, fp32 accum.
// 128x128 CTA tile, 8 warps (2x4), BK=16 (one m16n8k16 step), double-buffered.
// smem: 4 packed-bf16x2 planes [128][PLSTR] (A by row, B by n), hi and lo.
// ---------------------------------------------------------------------------
#define PLSTR 12                        // uint32 per plane row (8 used + pad)
#define PLANE (128*PLSTR)               // uint32 per plane
#define GM_SMEM (4*2*PLANE*4)           // 49152 bytes

template<int MODE, int NDIM>
__global__ __launch_bounds__(256) void mma_gemm(
    const float* __restrict__ A, const float* __restrict__ W,
    const float* __restrict__ bias,
    const float* __restrict__ grp, const float* __restrict__ gsp,
    float* __restrict__ outp)
{
    constexpr int K = 1024;
    extern __shared__ uint32_t smu[];
    uint32_t* AH = smu;                 // [2][128 r][PLSTR] k2-packed hi
    uint32_t* AL = AH + 2 * PLANE;
    uint32_t* BH = AL + 2 * PLANE;      // [2][128 n][PLSTR]
    uint32_t* BL = BH + 2 * PLANE;

    const float* Ap = (MODE == 2) ? g_ctx : A;

    int tid = threadIdx.x;
    int wid = tid >> 5, lane = tid & 31;
    int wr = wid >> 2, wc = wid & 3;
    int gid = lane >> 2, tig = lane & 3;
    int row0 = blockIdx.y * 128, col0 = blockIdx.x * 128;

    float acc[4][4][4];
    #pragma unroll
    for (int mt = 0; mt < 4; mt++)
        #pragma unroll
        for (int nt = 0; nt < 4; nt++)
            #pragma unroll
            for (int f = 0; f < 4; f++) acc[mt][nt][f] = 0.f;

    float4 pa[2];
    float  pbx[4], pby[4];

    auto ldg = [&](int kc) {
        int k0 = kc * 16;
        #pragma unroll
        for (int i = 0; i < 2; i++) {
            int idx = tid + i * 256;
            pa[i] = *(const float4*)(Ap + (size_t)(row0 + (idx >> 2)) * K + k0 + ((idx & 3) << 2));
        }
        #pragma unroll
        for (int t = 0; t < 4; t++) {
            int idx = tid + t * 256;          // 1024 (n, k2) tasks
            int n = idx & 127, k2 = idx >> 7; // k2 in 0..7
            const float* wp = W + (size_t)(k0 + 2 * k2) * NDIM + col0 + n;
            pbx[t] = wp[0];
            pby[t] = wp[NDIM];
        }
    };
    auto sts = [&](int buf) {
        #pragma unroll
        for (int i = 0; i < 2; i++) {
            int idx = tid + i * 256;
            int r = idx >> 2, k2 = (idx & 3) << 1;   // two k2 slots
            uint32_t h0, l0, h1, l1;
            splitbf2(pa[i].x, pa[i].y, h0, l0);
            splitbf2(pa[i].z, pa[i].w, h1, l1);
            int o = buf * PLANE + r * PLSTR + k2;
            AH[o] = h0; AH[o + 1] = h1;
            AL[o] = l0; AL[o + 1] = l1;
        }
        #pragma unroll
        for (int t = 0; t < 4; t++) {
            int idx = tid + t * 256;
            int n = idx & 127, k2 = idx >> 7;
            uint32_t h, l;
            splitbf2(pbx[t], pby[t], h, l);
            int o = buf * PLANE + n * PLSTR + k2;
            BH[o] = h; BL[o] = l;
        }
    };

    ldg(0); sts(0);
    __syncthreads();

    for (int kc = 0; kc < 64; kc++) {
        int cb = kc & 1;
        if (kc < 63) ldg(kc + 1);

        uint32_t aH[4][4], aL[4][4], bHf[4][2], bLf[4][2];
        #pragma unroll
        for (int mt = 0; mt < 4; mt++) {
            int r = wr * 64 + mt * 16 + gid;
            int base = cb * PLANE + r * PLSTR + tig;
            aH[mt][0] = AH[base];
            aH[mt][1] = AH[base + 8 * PLSTR];
            aH[mt][2] = AH[base + 4];
            aH[mt][3] = AH[base + 8 * PLSTR + 4];
            aL[mt][0] = AL[base];
            aL[mt][1] = AL[base + 8 * PLSTR];
            aL[mt][2] = AL[base + 4];
            aL[mt][3] = AL[base + 8 * PLSTR + 4];
        }
        #pragma unroll
        for (int nt = 0; nt < 4; nt++) {
            int n = wc * 32 + nt * 8 + gid;
            int base = cb * PLANE + n * PLSTR + tig;
            bHf[nt][0] = BH[base];
            bHf[nt][1] = BH[base + 4];
            bLf[nt][0] = BL[base];
            bLf[nt][1] = BL[base + 4];
        }
        #pragma unroll
        for (int mt = 0; mt < 4; mt++)
            #pragma unroll
            for (int nt = 0; nt < 4; nt++) {
                mma16(acc[mt][nt], aH[mt], bHf[nt]);
                mma16(acc[mt][nt], aL[mt], bHf[nt]);
                mma16(acc[mt][nt], aH[mt], bLf[nt]);
            }

        if (kc < 63) {
            sts((kc + 1) & 1);
            __syncthreads();
        }
    }

    float gr = 0.f, gs = 0.f;
    if (MODE == 1 || MODE == 2) { gr = *grp; gs = *gsp; }

    #pragma unroll
    for (int mt = 0; mt < 4; mt++) {
        #pragma unroll
        for (int nt = 0; nt < 4; nt++) {
            int rb = row0 + wr * 64 + mt * 16;
            int cb2 = col0 + wc * 32 + nt * 8;
            #pragma unroll
            for (int half = 0; half < 2; half++) {
                int r = rb + gid + half * 8;
                int b = r >> 11, s = r & (S_LEN - 1);
                #pragma unroll
                for (int e = 0; e < 2; e++) {
                    int c = cb2 + tig * 2 + e;
                    float v = acc[mt][nt][half * 2 + e];
                    if (MODE == 0) {
                        v += bias[c];
                        if (c < EMB) {
                            int h = c >> 6, d = c & 63;
                            g_q[(((size_t)(b * HEADS + h)) * S_LEN + s) * HDIM + d] = v * 0.125f;
                        } else {
                            int c2 = c - EMB;
                            int h = c2 >> 6, d = c2 & 63;
                            g_k[(((size_t)(b * HEADS + h)) * S_LEN + s) * HDIM + d] = v;
                        }
                    } else if (MODE == 1) {
                        int h = c >> 6, d = c & 63;
                        g_v[(((size_t)(b * HEADS + h)) * S_LEN + s) * HDIM + d] =
                            gr * v + gs * A[(size_t)r * K + c];
                    } else {
                        outp[(size_t)r * NDIM + c] =
                            gr * v + gs * g_ctx[(size_t)r * K + c];
                    }
                }
            }
        }
    }
}

// ---------------------------------------------------------------------------
// Fused V prefix-sum (unchanged, overlapped with QK GEMM)
// ---------------------------------------------------------------------------
__global__ __launch_bounds__(512) void vprefix2_k() {
    __shared__ float4 part[32][16];
    int bh = blockIdx.x;
    int ci = threadIdx.x >> 4;
    int dg = threadIdx.x & 15;

    const float4* vp = (const float4*)(g_v + ((size_t)bh * S_LEN + ci * 64) * 64) + dg;
    float4 acc = make_float4(0.f, 0.f, 0.f, 0.f);
    #pragma unroll 8
    for (int s = 0; s < 64; s++) {
        float4 t = vp[(size_t)s * 16];
        acc.x += t.x; acc.y += t.y; acc.z += t.z; acc.w += t.w;
    }
    part[ci][dg] = acc;
    __syncthreads();

    float4 base = make_float4(0.f, 0.f, 0.f, 0.f);
    for (int t = 0; t < ci; t++) {
        float4 p = part[t][dg];
        base.x += p.x; base.y += p.y; base.z += p.z; base.w += p.w;
    }

    float4* op = (float4*)(g_vs + ((size_t)bh * S_LEN + ci * 64) * 64) + dg;
    acc = base;
    #pragma unroll 8
    for (int s = 0; s < 64; s++) {
        float4 t = vp[(size_t)s * 16];
        acc.x += t.x; acc.y += t.y; acc.z += t.z; acc.w += t.w;
        op[(size_t)s * 16] = acc;
    }
}

// ---------------------------------------------------------------------------
// Tensor-core flash attention: QK^T in tf32x3, P@V in single tf32 (unchanged).
// ---------------------------------------------------------------------------
#define KTSTR 136
#define VSTR  72
#define PSTR  68
#define KTBUF (64*KTSTR)
#define VBUF  (64*VSTR)
#define FL2_SMEM ((2*KTBUF + 2*VBUF + 128*PSTR) * 4)   // 141312 B
#define NEG_BIG (-1.0e30f)

__global__ __launch_bounds__(256) void flash_mma(
    const float* __restrict__ gr_, const float* __restrict__ gs_,
    const float* __restrict__ gc_)
{
    extern __shared__ float smf[];
    float* KTb = smf;                    // [2][64 d][KTSTR]  K transposed {hi,lo}
    float* Vb  = smf + 2 * KTBUF;        // [2][64 k][VSTR]   V hi-only
    float* PT  = smf + 2 * KTBUF + 2 * VBUF;   // [128 q][PSTR]  P hi-only

    int tid = threadIdx.x, wid = tid >> 5, lane = tid & 31;
    int gid = lane >> 2, tig = lane & 3;
    int qt = 15 - (int)blockIdx.x;       // big workloads first
    int bh = blockIdx.y;
    int qbase = qt * 128;
    int rAp = wid * 8 + gid, rBp = 64 + wid * 8 + gid;
    int qA = qbase + rAp, qB = qbase + rBp;

    uint32_t qh[8][4], ql[8][4];
    {
        const float* Qp = g_q + (size_t)bh * S_LEN * 64;
        #pragma unroll
        for (int k8 = 0; k8 < 8; k8++) {
            float v[4];
            v[0] = Qp[(size_t)qA * 64 + k8 * 8 + tig];
            v[1] = Qp[(size_t)qB * 64 + k8 * 8 + tig];
            v[2] = Qp[(size_t)qA * 64 + k8 * 8 + tig + 4];
            v[3] = Qp[(size_t)qB * 64 + k8 * 8 + tig + 4];
            #pragma unroll
            for (int j = 0; j < 4; j++) {
                qh[k8][j] = f2tf32(v[j]);
                ql[k8][j] = f2tf32(v[j] - __uint_as_float(qh[k8][j]));
            }
        }
    }

    float O[8][4];
    #pragma unroll
    for (int nf = 0; nf < 8; nf++)
        #pragma unroll
        for (int f = 0; f < 4; f++) O[nf][f] = 0.f;
    float mA = NEG_BIG, mB = NEG_BIG, lA = 0.f, lB = 0.f;

    const int kmax = 2 * qt + 2;

    float  kst[16];
    float4 vst[4];
    auto ldgKV = [&](int kt) {
        const float* Kg = g_k + ((size_t)bh * S_LEN + kt * 64) * 64;
        const float* Vg = g_v + ((size_t)bh * S_LEN + kt * 64) * 64;
        #pragma unroll
        for (int i = 0; i < 4; i++) {
            int idx = tid + i * 256;
            int d = idx & 63, kp4 = (idx >> 6) << 2;
            #pragma unroll
            for (int j = 0; j < 4; j++)
                kst[i * 4 + j] = Kg[(size_t)(kp4 + j) * 64 + d];
            int vk = idx >> 4, d4 = (idx & 15) << 2;
            vst[i] = *(const float4*)(Vg + (size_t)vk * 64 + d4);
        }
    };
    auto stsKV = [&](int buf) {
        float* kb0 = KTb + buf * KTBUF;
        float* vb0 = Vb + buf * VBUF;
        #pragma unroll
        for (int i = 0; i < 4; i++) {
            int idx = tid + i * 256;
            int d = idx & 63, kp4 = (idx >> 6) << 2;
            float4 kv = make_float4(kst[i*4], kst[i*4+1], kst[i*4+2], kst[i*4+3]);
            uint4 kh, kl; split4(kv, kh, kl);
            float* kp = kb0 + d * KTSTR + kp4 * 2;
            *(float4*)kp = make_float4(__uint_as_float(kh.x), __uint_as_float(kl.x),
                                       __uint_as_float(kh.y), __uint_as_float(kl.y));
            *(float4*)(kp + 4) = make_float4(__uint_as_float(kh.z), __uint_as_float(kl.z),
                                             __uint_as_float(kh.w), __uint_as_float(kl.w));
            int vk = idx >> 4, d4 = (idx & 15) << 2;
            float4 vh4;
            vh4.x = __uint_as_float(f2tf32(vst[i].x));
            vh4.y = __uint_as_float(f2tf32(vst[i].y));
            vh4.z = __uint_as_float(f2tf32(vst[i].z));
            vh4.w = __uint_as_float(f2tf32(vst[i].w));
            *(float4*)(vb0 + vk * VSTR + d4) = vh4;
        }
    };

    ldgKV(0); stsKV(0);
    __syncthreads();

    for (int kt = 0; kt < kmax; kt++) {
        int buf = kt & 1;

        // S = Q @ K^T (tf32x3)
        float sacc[8][4];
        #pragma unroll
        for (int nf = 0; nf < 8; nf++)
            #pragma unroll
            for (int f = 0; f < 4; f++) sacc[nf][f] = 0.f;
        {
            const float* kb = KTb + buf * KTBUF;
            #pragma unroll
            for (int k8 = 0; k8 < 8; k8++) {
                #pragma unroll
                for (int nf = 0; nf < 8; nf++) {
                    float2 b0 = *(const float2*)(kb + (k8*8 + tig) * KTSTR + (nf*8 + gid) * 2);
                    float2 b1 = *(const float2*)(kb + (k8*8 + tig + 4) * KTSTR + (nf*8 + gid) * 2);
                    uint32_t bhv[2] = {__float_as_uint(b0.x), __float_as_uint(b1.x)};
                    uint32_t blv[2] = {__float_as_uint(b0.y), __float_as_uint(b1.y)};
                    mma8(sacc[nf], qh[k8], bhv);
                    mma8(sacc[nf], ql[k8], bhv);
                    mma8(sacc[nf], qh[k8], blv);
                }
            }
        }

        if (kt + 1 < kmax) ldgKV(kt + 1);

        if (kt >= 2 * qt) {
            int c0g = kt * 64;
            #pragma unroll
            for (int nf = 0; nf < 8; nf++)
                #pragma unroll
                for (int e = 0; e < 2; e++) {
                    int col = c0g + nf * 8 + tig * 2 + e;
                    if (col > qA) sacc[nf][e]     = NEG_BIG;
                    if (col > qB) sacc[nf][2 + e] = NEG_BIG;
                }
        }

        float mxA = NEG_BIG, mxB = NEG_BIG;
        #pragma unroll
        for (int nf = 0; nf < 8; nf++) {
            mxA = fmaxf(mxA, fmaxf(sacc[nf][0], sacc[nf][1]));
            mxB = fmaxf(mxB, fmaxf(sacc[nf][2], sacc[nf][3]));
        }
        mxA = fmaxf(mxA, __shfl_xor_sync(0xffffffffu, mxA, 1));
        mxA = fmaxf(mxA, __shfl_xor_sync(0xffffffffu, mxA, 2));
        mxB = fmaxf(mxB, __shfl_xor_sync(0xffffffffu, mxB, 1));
        mxB = fmaxf(mxB, __shfl_xor_sync(0xffffffffu, mxB, 2));
        float mnA = fmaxf(mA, mxA), mnB = fmaxf(mB, mxB);
        float scA = fexp(mA - mnA), scB = fexp(mB - mnB);
        mA = mnA; mB = mnB;
        float sumA = 0.f, sumB = 0.f;
        #pragma unroll
        for (int nf = 0; nf < 8; nf++) {
            float p0 = fexp(sacc[nf][0] - mnA);
            float p1 = fexp(sacc[nf][1] - mnA);
            float p2 = fexp(sacc[nf][2] - mnB);
            float p3 = fexp(sacc[nf][3] - mnB);
            sumA += p0 + p1; sumB += p2 + p3;
            int colo = nf * 8 + tig * 2;
            *(float2*)(PT + rAp * PSTR + colo) =
                make_float2(__uint_as_float(f2tf32(p0)), __uint_as_float(f2tf32(p1)));
            *(float2*)(PT + rBp * PSTR + colo) =
                make_float2(__uint_as_float(f2tf32(p2)), __uint_as_float(f2tf32(p3)));
        }
        sumA += __shfl_xor_sync(0xffffffffu, sumA, 1);
        sumA += __shfl_xor_sync(0xffffffffu, sumA, 2);
        sumB += __shfl_xor_sync(0xffffffffu, sumB, 1);
        sumB += __shfl_xor_sync(0xffffffffu, sumB, 2);
        lA = lA * scA + sumA;
        lB = lB * scB + sumB;
        #pragma unroll
        for (int nf = 0; nf < 8; nf++) {
            O[nf][0] *= scA; O[nf][1] *= scA;
            O[nf][2] *= scB; O[nf][3] *= scB;
        }
        __syncwarp();

        if (kt + 1 < kmax) stsKV((kt + 1) & 1);

        // O += P @ V  (single tf32: P hi, V hi)
        {
            const float* vb = Vb + buf * VBUF;
            #pragma unroll
            for (int k8 = 0; k8 < 8; k8++) {
                uint32_t ap[4];
                ap[0] = __float_as_uint(PT[rAp * PSTR + k8 * 8 + tig]);
                ap[1] = __float_as_uint(PT[rBp * PSTR + k8 * 8 + tig]);
                ap[2] = __float_as_uint(PT[rAp * PSTR + k8 * 8 + tig + 4]);
                ap[3] = __float_as_uint(PT[rBp * PSTR + k8 * 8 + tig + 4]);
                #pragma unroll
                for (int nf = 0; nf < 8; nf++) {
                    uint32_t bv[2];
                    bv[0] = __float_as_uint(vb[(k8*8 + tig) * VSTR + nf*8 + gid]);
                    bv[1] = __float_as_uint(vb[(k8*8 + tig + 4) * VSTR + nf*8 + gid]);
                    mma8(O[nf], ap, bv);
                }
            }
        }
        __syncthreads();
    }

    int h = bh & (HEADS - 1), b = bh >> 4;
    float grh = gr_[h], gsh = gs_[h], gch = gc_[h];
    float giA = grh / lA, giB = grh / lB;
    float cgA = gch / (float)(qA + 1), cgB = gch / (float)(qB + 1);
    const float* vrA  = g_v  + ((size_t)bh * S_LEN + qA) * 64;
    const float* vrB  = g_v  + ((size_t)bh * S_LEN + qB) * 64;
    const float* vsA  = g_vs + ((size_t)bh * S_LEN + qA) * 64;
    const float* vsB  = g_vs + ((size_t)bh * S_LEN + qB) * 64;
    float* oA = g_ctx + ((size_t)(b * S_LEN + qA)) * EMB + h * 64;
    float* oB = g_ctx + ((size_t)(b * S_LEN + qB)) * EMB + h * 64;
    #pragma unroll
    for (int nf = 0; nf < 8; nf++) {
        int d0 = nf * 8 + tig * 2;
        float2 vqA = *(const float2*)(vrA + d0);
        float2 vqB = *(const float2*)(vrB + d0);
        float2 psA = *(const float2*)(vsA + d0);
        float2 psB = *(const float2*)(vsB + d0);
        float2 ra, rb;
        ra.x = O[nf][0] * giA + gsh * vqA.x - cgA * psA.x;
        ra.y = O[nf][1] * giA + gsh * vqA.y - cgA * psA.y;
        rb.x = O[nf][2] * giB + gsh * vqB.x - cgB * psB.x;
        rb.y = O[nf][3] * giB + gsh * vqB.y - cgB * psB.y;
        *(float2*)(oA + d0) = ra;
        *(float2*)(oB + d0) = rb;
    }
}

// ---------------------------------------------------------------------------
extern "C" void kernel_launch(void* const* d_in, const int* in_sizes, int n_in,
                              void* d_out, int out_size)
{
    const float* hs   = (const float*)d_in[0];
    const float* qkw  = (const float*)d_in[1];
    const float* qkb  = (const float*)d_in[2];
    const float* vw   = (const float*)d_in[3];
    const float* vrg  = (const float*)d_in[4];
    const float* vsg  = (const float*)d_in[5];
    const float* pw   = (const float*)d_in[6];
    const float* prg  = (const float*)d_in[7];
    const float* psg  = (const float*)d_in[8];
    const float* amr  = (const float*)d_in[9];
    const float* ams  = (const float*)d_in[10];
    const float* cag  = (const float*)d_in[11];
    float* out = (float*)d_out;

    static cudaStream_t s2 = nullptr;
    static cudaEvent_t evV = nullptr, evP = nullptr;
    if (s2 == nullptr) {
        cudaStreamCreateWithFlags(&s2, cudaStreamNonBlocking);
        cudaEventCreateWithFlags(&evV, cudaEventDisableTiming);
        cudaEventCreateWithFlags(&evP, cudaEventDisableTiming);
    }

    cudaFuncSetAttribute(mma_gemm<0, 2048>, cudaFuncAttributeMaxDynamicSharedMemorySize, GM_SMEM);
    cudaFuncSetAttribute(mma_gemm<1, 1024>, cudaFuncAttributeMaxDynamicSharedMemorySize, GM_SMEM);
    cudaFuncSetAttribute(mma_gemm<2, 1024>, cudaFuncAttributeMaxDynamicSharedMemorySize, GM_SMEM);
    cudaFuncSetAttribute(flash_mma, cudaFuncAttributeMaxDynamicSharedMemorySize, FL2_SMEM);

    dim3 thr(256);
    // V projection first (producer of g_v)
    mma_gemm<1, 1024><<<dim3(1024 / 128, NROWS / 128), thr, GM_SMEM>>>(
        hs, vw, nullptr, vrg, vsg, nullptr);
    // Fork: V prefix-sum on side stream, overlapped with QK projection
    cudaEventRecord(evV, 0);
    cudaStreamWaitEvent(s2, evV, 0);
    vprefix2_k<<<BATCH * HEADS, 512, 0, s2>>>();
    // QK projection on main stream
    mma_gemm<0, 2048><<<dim3(2048 / 128, NROWS / 128), thr, GM_SMEM>>>(
        hs, qkw, qkb, nullptr, nullptr, nullptr);
    // Join
    cudaEventRecord(evP, s2);
    cudaStreamWaitEvent(0, evP, 0);
    // Tensor-core flash attention
    flash_mma<<<dim3(S_LEN / 128, BATCH * HEADS), thr, FL2_SMEM>>>(amr, ams, cag);
    // Output projection
    mma_gemm<2, 1024><<<dim3(1024 / 128, NROWS / 128), thr, GM_SMEM>>>(
        nullptr, pw, nullptr, prg, psg, out);
}